// round 10
// baseline (speedup 1.0000x reference)
#include <cuda_runtime.h>
#include <cuda_bf16.h>
#include <mma.h>
#include <cstdint>

using namespace nvcuda;

#define NEDGES 65536
#define NNODES 50000
#define DNODE  1024
#define DHID   1024

// ---------------------------------------------------------------------------
// Device scratch (static). Referenced ONLY from device code — passing a
// __device__ array as a kernel argument from host passes the host shadow
// address (GB300/ATS silently writes host memory!).
// ---------------------------------------------------------------------------
__device__ __nv_bfloat16 g_nf_hi[(size_t)NNODES * DNODE];
__device__ __nv_bfloat16 g_nf_lo[(size_t)NNODES * DNODE];
__device__ __nv_bfloat16 g_W1T_hi[(size_t)DHID * (2 * DNODE)];   // [N=1024][K=2048]
__device__ __nv_bfloat16 g_W1T_lo[(size_t)DHID * (2 * DNODE)];
__device__ __nv_bfloat16 g_W2T_hi[(size_t)DHID * DHID];          // [N=1024][K=1024]
__device__ __nv_bfloat16 g_W2T_lo[(size_t)DHID * DHID];
__device__ __nv_bfloat16 g_H_hi[(size_t)NEDGES * DHID];
__device__ __nv_bfloat16 g_H_lo[(size_t)NEDGES * DHID];

__device__ __forceinline__ void split1(float x, __nv_bfloat16& h, __nv_bfloat16& l) {
    h = __float2bfloat16(x);
    l = __float2bfloat16(x - __bfloat162float(h));
}

__device__ __forceinline__ uint32_t smem_u32(const void* p) {
    uint32_t a;
    asm("{ .reg .u64 t; cvta.to.shared.u64 t, %1; cvt.u32.u64 %0, t; }" : "=r"(a) : "l"(p));
    return a;
}
__device__ __forceinline__ void cp16(uint32_t saddr, const void* g) {
    asm volatile("cp.async.cg.shared.global [%0], [%1], 16;" :: "r"(saddr), "l"(g));
}
__device__ __forceinline__ void cp_commit() {
    asm volatile("cp.async.commit_group;");
}
template<int N>
__device__ __forceinline__ void cp_wait() {
    asm volatile("cp.async.wait_group %0;" :: "n"(N));
}

// ---------------------------------------------------------------------------
// Pre-pass kernels (globals written device-side)
// ---------------------------------------------------------------------------
__global__ void split_nf_kernel(const float4* __restrict__ in, int n4)
{
    int id = blockIdx.x * blockDim.x + threadIdx.x;
    if (id >= n4) return;
    float4 v = in[id];
    __nv_bfloat16 h0, h1, h2, h3, l0, l1, l2, l3;
    split1(v.x, h0, l0); split1(v.y, h1, l1);
    split1(v.z, h2, l2); split1(v.w, h3, l3);
    uint32_t ph0 = (uint32_t)__bfloat16_as_ushort(h0) | ((uint32_t)__bfloat16_as_ushort(h1) << 16);
    uint32_t ph1 = (uint32_t)__bfloat16_as_ushort(h2) | ((uint32_t)__bfloat16_as_ushort(h3) << 16);
    uint32_t pl0 = (uint32_t)__bfloat16_as_ushort(l0) | ((uint32_t)__bfloat16_as_ushort(l1) << 16);
    uint32_t pl1 = (uint32_t)__bfloat16_as_ushort(l2) | ((uint32_t)__bfloat16_as_ushort(l3) << 16);
    *reinterpret_cast<uint2*>(g_nf_hi + 4 * (size_t)id) = make_uint2(ph0, ph1);
    *reinterpret_cast<uint2*>(g_nf_lo + 4 * (size_t)id) = make_uint2(pl0, pl1);
}

template<int WHICH>
__global__ void transpose_split_kernel(const float* __restrict__ W)
{
    constexpr int K = (WHICH == 1) ? 2 * DNODE : DHID;
    constexpr int KSHIFT = (WHICH == 1) ? 11 : 10;
    __nv_bfloat16* hi = (WHICH == 1) ? g_W1T_hi : g_W2T_hi;
    __nv_bfloat16* lo = (WHICH == 1) ? g_W1T_lo : g_W2T_lo;
    size_t id = (size_t)blockIdx.x * blockDim.x + threadIdx.x;
    if (id >= (size_t)K * DHID) return;
    int k = (int)(id & (size_t)(K - 1));
    int n = (int)(id >> KSHIFT);
    float x = W[(size_t)k * DHID + n];
    __nv_bfloat16 h, l;
    split1(x, h, l);
    hi[id] = h;
    lo[id] = l;
}

// ---------------------------------------------------------------------------
// Split-bf16 WMMA GEMM v4.
//   BM=128, BN=128, BK=32; 8 warps (4m x 2n), warp tile 32x64 (2x4 frags).
//   cp.async double-buffered with ONE __syncthreads per k-tile:
//     wait<0>; barrier; issue(i+1); compute(i)
//   The barrier both publishes tile i and orders compute(i-1) before the
//   cp.async overwrite of its buffer. 2 CTAs/SM (16 warps/SM).
// ---------------------------------------------------------------------------
static constexpr int LDT  = 40;                 // bf16 elems per smem row (80B)
static constexpr int MBUF = 128 * LDT * 2;      // 10240 B: one matrix buffer
static constexpr int SBUF = 4 * MBUF;           // 40960 B: Ah|Al|Bh|Bl
static constexpr int HDR  = 1536;               // s_src 512 | s_dst 512 | s_bias 512
static constexpr int SMEM_BYTES = HDR + 2 * SBUF;   // 83456

template<int KTOT, bool STAGE1>
__global__ __launch_bounds__(256, 2)
void gemm_kernel(const int* __restrict__ src, const int* __restrict__ dst,
                 const float* __restrict__ bias, float* __restrict__ out)
{
    extern __shared__ char smem[];
    int*   s_src  = (int*)smem;
    int*   s_dst  = (int*)(smem + 512);
    float* s_bias = (float*)(smem + 1024);
    char*  tiles  = smem + HDR;
    const uint32_t tiles_u32 = smem_u32(tiles);

    const int tid  = threadIdx.x;
    const int lane = tid & 31;
    const int wid  = tid >> 5;
    const int wm   = wid & 3;      // 4 warps along M (32 rows each)
    const int wn   = wid >> 2;     // 2 warps along N (64 cols each)
    const int m0 = blockIdx.y * 128;
    const int n0 = blockIdx.x * 128;

    if (tid < 128) {
        if (STAGE1) {
            s_src[tid] = src[m0 + tid];
            s_dst[tid] = dst[m0 + tid];
        }
        s_bias[tid] = bias[n0 + tid];
    }
    __syncthreads();

    const __nv_bfloat16* Ahi = STAGE1 ? g_nf_hi : g_H_hi;
    const __nv_bfloat16* Alo = STAGE1 ? g_nf_lo : g_H_lo;
    const __nv_bfloat16* Bhi = STAGE1 ? g_W1T_hi : g_W2T_hi;
    const __nv_bfloat16* Blo = STAGE1 ? g_W1T_lo : g_W2T_lo;

    constexpr int NT = KTOT / 32;

    wmma::fragment<wmma::accumulator, 16, 16, 16, float> acc[2][4];
    #pragma unroll
    for (int i = 0; i < 2; ++i)
        #pragma unroll
        for (int j = 0; j < 4; ++j)
            wmma::fill_fragment(acc[i][j], 0.0f);

    // cp.async one k-tile into stage s. 256 threads: thread t -> row t/2,
    // 32B half (t&1) of the 64B row, for Ah/Al/Bh/Bl (8 x 16B chunks).
    auto issue_tile = [&](int kt, int s) {
        const int kglob = kt * 32;
        const int row  = tid >> 1;
        const int half = (tid & 1) * 16;   // bf16 elem offset within 32-elem row
        const uint32_t base = tiles_u32 + s * SBUF + row * (LDT * 2) + half * 2;
        size_t gA;
        if (STAGE1) {
            const int* sidx = (kglob < DNODE) ? s_src : s_dst;
            gA = ((size_t)sidx[row] << 10) + (kglob & (DNODE - 1)) + half;
        } else {
            gA = ((size_t)(m0 + row) << 10) + kglob + half;
        }
        const size_t gB = (size_t)(n0 + row) * KTOT + kglob + half;
        #pragma unroll
        for (int ch = 0; ch < 2; ++ch) {
            cp16(base + 0 * MBUF + ch * 16, Ahi + gA + ch * 8);
            cp16(base + 1 * MBUF + ch * 16, Alo + gA + ch * 8);
            cp16(base + 2 * MBUF + ch * 16, Bhi + gB + ch * 8);
            cp16(base + 3 * MBUF + ch * 16, Blo + gB + ch * 8);
        }
    };

    auto compute = [&](int s) {
        const __nv_bfloat16* Ah = (const __nv_bfloat16*)(tiles + s * SBUF + 0 * MBUF);
        const __nv_bfloat16* Al = (const __nv_bfloat16*)(tiles + s * SBUF + 1 * MBUF);
        const __nv_bfloat16* Bh = (const __nv_bfloat16*)(tiles + s * SBUF + 2 * MBUF);
        const __nv_bfloat16* Bl = (const __nv_bfloat16*)(tiles + s * SBUF + 3 * MBUF);
        #pragma unroll
        for (int kk = 0; kk < 2; ++kk) {
            wmma::fragment<wmma::matrix_a, 16, 16, 16, __nv_bfloat16, wmma::row_major> ah[2], al[2];
            #pragma unroll
            for (int mi = 0; mi < 2; ++mi) {
                const int r = wm * 32 + mi * 16;
                wmma::load_matrix_sync(ah[mi], Ah + r * LDT + kk * 16, LDT);
                wmma::load_matrix_sync(al[mi], Al + r * LDT + kk * 16, LDT);
            }
            #pragma unroll
            for (int nj = 0; nj < 4; ++nj) {
                wmma::fragment<wmma::matrix_b, 16, 16, 16, __nv_bfloat16, wmma::col_major> bh, bl;
                const int r = wn * 64 + nj * 16;
                wmma::load_matrix_sync(bh, Bh + r * LDT + kk * 16, LDT);
                wmma::load_matrix_sync(bl, Bl + r * LDT + kk * 16, LDT);
                #pragma unroll
                for (int mi = 0; mi < 2; ++mi) {
                    wmma::mma_sync(acc[mi][nj], ah[mi], bh, acc[mi][nj]);
                    wmma::mma_sync(acc[mi][nj], ah[mi], bl, acc[mi][nj]);
                    wmma::mma_sync(acc[mi][nj], al[mi], bh, acc[mi][nj]);
                }
            }
        }
    };

    issue_tile(0, 0);
    cp_commit();
    for (int kt = 0; kt < NT; ++kt) {
        cp_wait<0>();        // tile kt landed (the only outstanding group)
        __syncthreads();     // publish tile kt; order compute(kt-1) before overwrite
        if (kt + 1 < NT) {
            issue_tile(kt + 1, (kt + 1) & 1);   // in flight during compute(kt)
            cp_commit();
        }
        compute(kt & 1);
    }
    __syncthreads();   // all compute done before tile smem reused as staging

    // ---- epilogue via store_matrix_sync staging (layout-assumption-free) ----
    float* stage = reinterpret_cast<float*>(tiles) + wid * 256;  // 1KB per warp
    const int lr = lane >> 1;
    const int lc = (lane & 1) * 8;

    #pragma unroll
    for (int mi = 0; mi < 2; ++mi) {
        #pragma unroll
        for (int nj = 0; nj < 4; ++nj) {
            wmma::store_matrix_sync(stage, acc[mi][nj], 16, wmma::mem_row_major);
            __syncwarp();
            const int r  = m0 + wm * 32 + mi * 16 + lr;
            const int cL = wn * 64 + nj * 16 + lc;
            float v[8];
            #pragma unroll
            for (int j = 0; j < 8; ++j)
                v[j] = stage[lr * 16 + lc + j] + s_bias[cL + j];

            const size_t o = ((size_t)r << 10) + n0 + cL;
            if (STAGE1) {
                uint32_t ph[4], pl[4];
                #pragma unroll
                for (int j = 0; j < 8; j += 2) {
                    float v0 = v[j] > 0.0f ? v[j] : 0.0f;
                    float v1 = v[j + 1] > 0.0f ? v[j + 1] : 0.0f;
                    __nv_bfloat16 h0, h1, l0, l1;
                    split1(v0, h0, l0);
                    split1(v1, h1, l1);
                    ph[j >> 1] = (uint32_t)__bfloat16_as_ushort(h0) |
                                 ((uint32_t)__bfloat16_as_ushort(h1) << 16);
                    pl[j >> 1] = (uint32_t)__bfloat16_as_ushort(l0) |
                                 ((uint32_t)__bfloat16_as_ushort(l1) << 16);
                }
                *reinterpret_cast<uint4*>(g_H_hi + o) = make_uint4(ph[0], ph[1], ph[2], ph[3]);
                *reinterpret_cast<uint4*>(g_H_lo + o) = make_uint4(pl[0], pl[1], pl[2], pl[3]);
            } else {
                float4* d4 = reinterpret_cast<float4*>(out + o);
                d4[0] = make_float4(v[0], v[1], v[2], v[3]);
                d4[1] = make_float4(v[4], v[5], v[6], v[7]);
            }
            __syncwarp();
        }
    }
}

// ---------------------------------------------------------------------------
extern "C" void kernel_launch(void* const* d_in, const int* in_sizes, int n_in,
                              void* d_out, int out_size)
{
    const float* nf  = (const float*)d_in[0];
    const int*   src = (const int*)d_in[1];   // JAX int64 downcasts to int32 (x64 off)
    const int*   dst = (const int*)d_in[2];
    const float* W1  = (const float*)d_in[3];
    const float* b1  = (const float*)d_in[4];
    const float* W2  = (const float*)d_in[5];
    const float* b2  = (const float*)d_in[6];
    float*       out = (float*)d_out;

    cudaFuncSetAttribute(gemm_kernel<2 * DNODE, true>,
                         cudaFuncAttributeMaxDynamicSharedMemorySize, SMEM_BYTES);
    cudaFuncSetAttribute(gemm_kernel<DHID, false>,
                         cudaFuncAttributeMaxDynamicSharedMemorySize, SMEM_BYTES);

    // 1) split node features into bf16 hi/lo
    {
        int n4 = (NNODES * DNODE) / 4;
        split_nf_kernel<<<(n4 + 255) / 256, 256>>>((const float4*)nf, n4);
    }
    // 2) transpose+split weights
    {
        size_t t1 = (size_t)(2 * DNODE) * DHID;
        transpose_split_kernel<1><<<(unsigned)((t1 + 255) / 256), 256>>>(W1);
        size_t t2 = (size_t)DHID * DHID;
        transpose_split_kernel<2><<<(unsigned)((t2 + 255) / 256), 256>>>(W2);
    }
    // 3) stage 1: H = relu(concat @ W1 + b1)  (K = 2048)
    {
        dim3 grid(DHID / 128, NEDGES / 128);
        gemm_kernel<2 * DNODE, true><<<grid, 256, SMEM_BYTES>>>(src, dst, b1, nullptr);
    }
    // 4) stage 2: out = H @ W2 + b2  (K = 1024)
    {
        dim3 grid(DHID / 128, NEDGES / 128);
        gemm_kernel<DHID, false><<<grid, 256, SMEM_BYTES>>>(src, dst, b2, out);
    }
}

// round 11
// speedup vs baseline: 1.0097x; 1.0097x over previous
#include <cuda_runtime.h>
#include <cuda_bf16.h>
#include <mma.h>
#include <cstdint>

using namespace nvcuda;

#define NEDGES 65536
#define NNODES 50000
#define DNODE  1024
#define DHID   1024

// ---------------------------------------------------------------------------
// Device scratch (static). Referenced ONLY from device code — passing a
// __device__ array as a kernel argument from host passes the host shadow
// address (GB300/ATS silently writes host memory!).
// ---------------------------------------------------------------------------
__device__ __nv_bfloat16 g_nf_hi[(size_t)NNODES * DNODE];
__device__ __nv_bfloat16 g_nf_lo[(size_t)NNODES * DNODE];
__device__ __nv_bfloat16 g_W1T_hi[(size_t)DHID * (2 * DNODE)];   // [N=1024][K=2048]
__device__ __nv_bfloat16 g_W1T_lo[(size_t)DHID * (2 * DNODE)];
__device__ __nv_bfloat16 g_W2T_hi[(size_t)DHID * DHID];          // [N=1024][K=1024]
__device__ __nv_bfloat16 g_W2T_lo[(size_t)DHID * DHID];
__device__ __nv_bfloat16 g_H_hi[(size_t)NEDGES * DHID];
__device__ __nv_bfloat16 g_H_lo[(size_t)NEDGES * DHID];

__device__ __forceinline__ void split1(float x, __nv_bfloat16& h, __nv_bfloat16& l) {
    h = __float2bfloat16(x);
    l = __float2bfloat16(x - __bfloat162float(h));
}

__device__ __forceinline__ uint32_t smem_u32(const void* p) {
    uint32_t a;
    asm("{ .reg .u64 t; cvta.to.shared.u64 t, %1; cvt.u32.u64 %0, t; }" : "=r"(a) : "l"(p));
    return a;
}
__device__ __forceinline__ void cp16(uint32_t saddr, const void* g) {
    asm volatile("cp.async.cg.shared.global [%0], [%1], 16;" :: "r"(saddr), "l"(g));
}
__device__ __forceinline__ void cp_commit() {
    asm volatile("cp.async.commit_group;");
}
template<int N>
__device__ __forceinline__ void cp_wait() {
    asm volatile("cp.async.wait_group %0;" :: "n"(N));
}

// ---------------------------------------------------------------------------
// Pre-pass kernels (globals written device-side)
// ---------------------------------------------------------------------------
__global__ void split_nf_kernel(const float4* __restrict__ in, int n4)
{
    int id = blockIdx.x * blockDim.x + threadIdx.x;
    if (id >= n4) return;
    float4 v = in[id];
    __nv_bfloat16 h0, h1, h2, h3, l0, l1, l2, l3;
    split1(v.x, h0, l0); split1(v.y, h1, l1);
    split1(v.z, h2, l2); split1(v.w, h3, l3);
    uint32_t ph0 = (uint32_t)__bfloat16_as_ushort(h0) | ((uint32_t)__bfloat16_as_ushort(h1) << 16);
    uint32_t ph1 = (uint32_t)__bfloat16_as_ushort(h2) | ((uint32_t)__bfloat16_as_ushort(h3) << 16);
    uint32_t pl0 = (uint32_t)__bfloat16_as_ushort(l0) | ((uint32_t)__bfloat16_as_ushort(l1) << 16);
    uint32_t pl1 = (uint32_t)__bfloat16_as_ushort(l2) | ((uint32_t)__bfloat16_as_ushort(l3) << 16);
    *reinterpret_cast<uint2*>(g_nf_hi + 4 * (size_t)id) = make_uint2(ph0, ph1);
    *reinterpret_cast<uint2*>(g_nf_lo + 4 * (size_t)id) = make_uint2(pl0, pl1);
}

template<int WHICH>
__global__ void transpose_split_kernel(const float* __restrict__ W)
{
    constexpr int K = (WHICH == 1) ? 2 * DNODE : DHID;
    constexpr int KSHIFT = (WHICH == 1) ? 11 : 10;
    __nv_bfloat16* hi = (WHICH == 1) ? g_W1T_hi : g_W2T_hi;
    __nv_bfloat16* lo = (WHICH == 1) ? g_W1T_lo : g_W2T_lo;
    size_t id = (size_t)blockIdx.x * blockDim.x + threadIdx.x;
    if (id >= (size_t)K * DHID) return;
    int k = (int)(id & (size_t)(K - 1));
    int n = (int)(id >> KSHIFT);
    float x = W[(size_t)k * DHID + n];
    __nv_bfloat16 h, l;
    split1(x, h, l);
    hi[id] = h;
    lo[id] = l;
}

// ---------------------------------------------------------------------------
// Split-bf16 WMMA GEMM v5.
//   BM=128, BN=128, BK=32; 8 warps (4m x 2n), warp tile 32x64 (2x4 frags).
//   cp.async double-buffered, one barrier per k-tile.
//   ILP-ordered mma schedule: each accumulator is touched once per term sweep
//   (8 independent HMMAs between dependent reuses, vs 1 before).
// ---------------------------------------------------------------------------
static constexpr int LDT  = 40;                 // bf16 elems per smem row (80B)
static constexpr int MBUF = 128 * LDT * 2;      // 10240 B: one matrix buffer
static constexpr int SBUF = 4 * MBUF;           // 40960 B: Ah|Al|Bh|Bl
static constexpr int HDR  = 1536;               // s_src 512 | s_dst 512 | s_bias 512
static constexpr int SMEM_BYTES = HDR + 2 * SBUF;   // 83456

template<int KTOT, bool STAGE1>
__global__ __launch_bounds__(256, 2)
void gemm_kernel(const int* __restrict__ src, const int* __restrict__ dst,
                 const float* __restrict__ bias, float* __restrict__ out)
{
    extern __shared__ char smem[];
    int*   s_src  = (int*)smem;
    int*   s_dst  = (int*)(smem + 512);
    float* s_bias = (float*)(smem + 1024);
    char*  tiles  = smem + HDR;
    const uint32_t tiles_u32 = smem_u32(tiles);

    const int tid  = threadIdx.x;
    const int lane = tid & 31;
    const int wid  = tid >> 5;
    const int wm   = wid & 3;      // 4 warps along M (32 rows each)
    const int wn   = wid >> 2;     // 2 warps along N (64 cols each)
    const int m0 = blockIdx.y * 128;
    const int n0 = blockIdx.x * 128;

    if (tid < 128) {
        if (STAGE1) {
            s_src[tid] = src[m0 + tid];
            s_dst[tid] = dst[m0 + tid];
        }
        s_bias[tid] = bias[n0 + tid];
    }
    __syncthreads();

    const __nv_bfloat16* Ahi = STAGE1 ? g_nf_hi : g_H_hi;
    const __nv_bfloat16* Alo = STAGE1 ? g_nf_lo : g_H_lo;
    const __nv_bfloat16* Bhi = STAGE1 ? g_W1T_hi : g_W2T_hi;
    const __nv_bfloat16* Blo = STAGE1 ? g_W1T_lo : g_W2T_lo;

    constexpr int NT = KTOT / 32;

    wmma::fragment<wmma::accumulator, 16, 16, 16, float> acc[2][4];
    #pragma unroll
    for (int i = 0; i < 2; ++i)
        #pragma unroll
        for (int j = 0; j < 4; ++j)
            wmma::fill_fragment(acc[i][j], 0.0f);

    // cp.async one k-tile into stage s. 256 threads: thread t -> row t/2,
    // 32B half (t&1) of the 64B row, for Ah/Al/Bh/Bl (8 x 16B chunks).
    auto issue_tile = [&](int kt, int s) {
        const int kglob = kt * 32;
        const int row  = tid >> 1;
        const int half = (tid & 1) * 16;   // bf16 elem offset within 32-elem row
        const uint32_t base = tiles_u32 + s * SBUF + row * (LDT * 2) + half * 2;
        size_t gA;
        if (STAGE1) {
            const int* sidx = (kglob < DNODE) ? s_src : s_dst;
            gA = ((size_t)sidx[row] << 10) + (kglob & (DNODE - 1)) + half;
        } else {
            gA = ((size_t)(m0 + row) << 10) + kglob + half;
        }
        const size_t gB = (size_t)(n0 + row) * KTOT + kglob + half;
        #pragma unroll
        for (int ch = 0; ch < 2; ++ch) {
            cp16(base + 0 * MBUF + ch * 16, Ahi + gA + ch * 8);
            cp16(base + 1 * MBUF + ch * 16, Alo + gA + ch * 8);
            cp16(base + 2 * MBUF + ch * 16, Bhi + gB + ch * 8);
            cp16(base + 3 * MBUF + ch * 16, Blo + gB + ch * 8);
        }
    };

    auto compute = [&](int s) {
        const __nv_bfloat16* Ah = (const __nv_bfloat16*)(tiles + s * SBUF + 0 * MBUF);
        const __nv_bfloat16* Al = (const __nv_bfloat16*)(tiles + s * SBUF + 1 * MBUF);
        const __nv_bfloat16* Bh = (const __nv_bfloat16*)(tiles + s * SBUF + 2 * MBUF);
        const __nv_bfloat16* Bl = (const __nv_bfloat16*)(tiles + s * SBUF + 3 * MBUF);
        #pragma unroll
        for (int kk = 0; kk < 2; ++kk) {
            wmma::fragment<wmma::matrix_a, 16, 16, 16, __nv_bfloat16, wmma::row_major> ah[2], al[2];
            wmma::fragment<wmma::matrix_b, 16, 16, 16, __nv_bfloat16, wmma::col_major> bf[4];
            #pragma unroll
            for (int mi = 0; mi < 2; ++mi) {
                const int r = wm * 32 + mi * 16;
                wmma::load_matrix_sync(ah[mi], Ah + r * LDT + kk * 16, LDT);
                wmma::load_matrix_sync(al[mi], Al + r * LDT + kk * 16, LDT);
            }
            #pragma unroll
            for (int nj = 0; nj < 4; ++nj)
                wmma::load_matrix_sync(bf[nj], Bh + (wn * 64 + nj * 16) * LDT + kk * 16, LDT);

            // term 1: Ah * Bh — 8 independent accumulators back-to-back
            #pragma unroll
            for (int mi = 0; mi < 2; ++mi)
                #pragma unroll
                for (int nj = 0; nj < 4; ++nj)
                    wmma::mma_sync(acc[mi][nj], ah[mi], bf[nj], acc[mi][nj]);
            // term 2: Al * Bh — acc reuse is 8 HMMAs apart
            #pragma unroll
            for (int mi = 0; mi < 2; ++mi)
                #pragma unroll
                for (int nj = 0; nj < 4; ++nj)
                    wmma::mma_sync(acc[mi][nj], al[mi], bf[nj], acc[mi][nj]);
            // reload B fragments as Bl, then term 3: Ah * Bl
            #pragma unroll
            for (int nj = 0; nj < 4; ++nj)
                wmma::load_matrix_sync(bf[nj], Bl + (wn * 64 + nj * 16) * LDT + kk * 16, LDT);
            #pragma unroll
            for (int mi = 0; mi < 2; ++mi)
                #pragma unroll
                for (int nj = 0; nj < 4; ++nj)
                    wmma::mma_sync(acc[mi][nj], ah[mi], bf[nj], acc[mi][nj]);
        }
    };

    issue_tile(0, 0);
    cp_commit();
    for (int kt = 0; kt < NT; ++kt) {
        cp_wait<0>();        // tile kt landed (the only outstanding group)
        __syncthreads();     // publish tile kt; order compute(kt-1) before overwrite
        if (kt + 1 < NT) {
            issue_tile(kt + 1, (kt + 1) & 1);   // in flight during compute(kt)
            cp_commit();
        }
        compute(kt & 1);
    }
    __syncthreads();   // all compute done before tile smem reused as staging

    // ---- epilogue via store_matrix_sync staging (layout-assumption-free) ----
    float* stage = reinterpret_cast<float*>(tiles) + wid * 256;  // 1KB per warp
    const int lr = lane >> 1;
    const int lc = (lane & 1) * 8;

    #pragma unroll
    for (int mi = 0; mi < 2; ++mi) {
        #pragma unroll
        for (int nj = 0; nj < 4; ++nj) {
            wmma::store_matrix_sync(stage, acc[mi][nj], 16, wmma::mem_row_major);
            __syncwarp();
            const int r  = m0 + wm * 32 + mi * 16 + lr;
            const int cL = wn * 64 + nj * 16 + lc;
            float v[8];
            #pragma unroll
            for (int j = 0; j < 8; ++j)
                v[j] = stage[lr * 16 + lc + j] + s_bias[cL + j];

            const size_t o = ((size_t)r << 10) + n0 + cL;
            if (STAGE1) {
                uint32_t ph[4], pl[4];
                #pragma unroll
                for (int j = 0; j < 8; j += 2) {
                    float v0 = v[j] > 0.0f ? v[j] : 0.0f;
                    float v1 = v[j + 1] > 0.0f ? v[j + 1] : 0.0f;
                    __nv_bfloat16 h0, h1, l0, l1;
                    split1(v0, h0, l0);
                    split1(v1, h1, l1);
                    ph[j >> 1] = (uint32_t)__bfloat16_as_ushort(h0) |
                                 ((uint32_t)__bfloat16_as_ushort(h1) << 16);
                    pl[j >> 1] = (uint32_t)__bfloat16_as_ushort(l0) |
                                 ((uint32_t)__bfloat16_as_ushort(l1) << 16);
                }
                *reinterpret_cast<uint4*>(g_H_hi + o) = make_uint4(ph[0], ph[1], ph[2], ph[3]);
                *reinterpret_cast<uint4*>(g_H_lo + o) = make_uint4(pl[0], pl[1], pl[2], pl[3]);
            } else {
                float4* d4 = reinterpret_cast<float4*>(out + o);
                d4[0] = make_float4(v[0], v[1], v[2], v[3]);
                d4[1] = make_float4(v[4], v[5], v[6], v[7]);
            }
            __syncwarp();
        }
    }
}

// ---------------------------------------------------------------------------
extern "C" void kernel_launch(void* const* d_in, const int* in_sizes, int n_in,
                              void* d_out, int out_size)
{
    const float* nf  = (const float*)d_in[0];
    const int*   src = (const int*)d_in[1];   // JAX int64 downcasts to int32 (x64 off)
    const int*   dst = (const int*)d_in[2];
    const float* W1  = (const float*)d_in[3];
    const float* b1  = (const float*)d_in[4];
    const float* W2  = (const float*)d_in[5];
    const float* b2  = (const float*)d_in[6];
    float*       out = (float*)d_out;

    cudaFuncSetAttribute(gemm_kernel<2 * DNODE, true>,
                         cudaFuncAttributeMaxDynamicSharedMemorySize, SMEM_BYTES);
    cudaFuncSetAttribute(gemm_kernel<DHID, false>,
                         cudaFuncAttributeMaxDynamicSharedMemorySize, SMEM_BYTES);

    // 1) split node features into bf16 hi/lo
    {
        int n4 = (NNODES * DNODE) / 4;
        split_nf_kernel<<<(n4 + 255) / 256, 256>>>((const float4*)nf, n4);
    }
    // 2) transpose+split weights
    {
        size_t t1 = (size_t)(2 * DNODE) * DHID;
        transpose_split_kernel<1><<<(unsigned)((t1 + 255) / 256), 256>>>(W1);
        size_t t2 = (size_t)DHID * DHID;
        transpose_split_kernel<2><<<(unsigned)((t2 + 255) / 256), 256>>>(W2);
    }
    // 3) stage 1: H = relu(concat @ W1 + b1)  (K = 2048)
    {
        dim3 grid(DHID / 128, NEDGES / 128);
        gemm_kernel<2 * DNODE, true><<<grid, 256, SMEM_BYTES>>>(src, dst, b1, nullptr);
    }
    // 4) stage 2: out = H @ W2 + b2  (K = 1024)
    {
        dim3 grid(DHID / 128, NEDGES / 128);
        gemm_kernel<DHID, false><<<grid, 256, SMEM_BYTES>>>(src, dst, b2, out);
    }
}

// round 12
// speedup vs baseline: 1.0194x; 1.0096x over previous
#include <cuda_runtime.h>
#include <cuda_bf16.h>
#include <cstdint>

#define NEDGES 65536
#define NNODES 50000
#define DNODE  1024
#define DHID   1024

// ---------------------------------------------------------------------------
// Device scratch (static). Referenced ONLY from device code — passing a
// __device__ array as a kernel argument from host passes the host shadow
// address (GB300/ATS silently writes host memory!).
// ---------------------------------------------------------------------------
__device__ __nv_bfloat16 g_nf_hi[(size_t)NNODES * DNODE];
__device__ __nv_bfloat16 g_nf_lo[(size_t)NNODES * DNODE];
__device__ __nv_bfloat16 g_W1T_hi[(size_t)DHID * (2 * DNODE)];   // [N=1024][K=2048]
__device__ __nv_bfloat16 g_W1T_lo[(size_t)DHID * (2 * DNODE)];
__device__ __nv_bfloat16 g_W2T_hi[(size_t)DHID * DHID];          // [N=1024][K=1024]
__device__ __nv_bfloat16 g_W2T_lo[(size_t)DHID * DHID];
__device__ __nv_bfloat16 g_H_hi[(size_t)NEDGES * DHID];
__device__ __nv_bfloat16 g_H_lo[(size_t)NEDGES * DHID];

__device__ __forceinline__ void split1(float x, __nv_bfloat16& h, __nv_bfloat16& l) {
    h = __float2bfloat16(x);
    l = __float2bfloat16(x - __bfloat162float(h));
}

__device__ __forceinline__ uint32_t smem_u32(const void* p) {
    uint32_t a;
    asm("{ .reg .u64 t; cvta.to.shared.u64 t, %1; cvt.u32.u64 %0, t; }" : "=r"(a) : "l"(p));
    return a;
}
__device__ __forceinline__ void cp16(uint32_t saddr, const void* g) {
    asm volatile("cp.async.cg.shared.global [%0], [%1], 16;" :: "r"(saddr), "l"(g));
}
__device__ __forceinline__ void cp_commit() {
    asm volatile("cp.async.commit_group;");
}
template<int N>
__device__ __forceinline__ void cp_wait() {
    asm volatile("cp.async.wait_group %0;" :: "n"(N));
}
__device__ __forceinline__ void ldsm4(uint32_t* r, uint32_t addr) {
    asm volatile("ldmatrix.sync.aligned.m8n8.x4.shared.b16 {%0,%1,%2,%3}, [%4];"
                 : "=r"(r[0]), "=r"(r[1]), "=r"(r[2]), "=r"(r[3]) : "r"(addr));
}
__device__ __forceinline__ void mma16816(float* c, const uint32_t* a,
                                         uint32_t b0, uint32_t b1) {
    asm volatile(
        "mma.sync.aligned.m16n8k16.row.col.f32.bf16.bf16.f32 "
        "{%0,%1,%2,%3}, {%4,%5,%6,%7}, {%8,%9}, {%0,%1,%2,%3};"
        : "+f"(c[0]), "+f"(c[1]), "+f"(c[2]), "+f"(c[3])
        : "r"(a[0]), "r"(a[1]), "r"(a[2]), "r"(a[3]), "r"(b0), "r"(b1));
}

// ---------------------------------------------------------------------------
// Pre-pass kernels (globals written device-side)
// ---------------------------------------------------------------------------
__global__ void split_nf_kernel(const float4* __restrict__ in, int n4)
{
    int id = blockIdx.x * blockDim.x + threadIdx.x;
    if (id >= n4) return;
    float4 v = in[id];
    __nv_bfloat16 h0, h1, h2, h3, l0, l1, l2, l3;
    split1(v.x, h0, l0); split1(v.y, h1, l1);
    split1(v.z, h2, l2); split1(v.w, h3, l3);
    uint32_t ph0 = (uint32_t)__bfloat16_as_ushort(h0) | ((uint32_t)__bfloat16_as_ushort(h1) << 16);
    uint32_t ph1 = (uint32_t)__bfloat16_as_ushort(h2) | ((uint32_t)__bfloat16_as_ushort(h3) << 16);
    uint32_t pl0 = (uint32_t)__bfloat16_as_ushort(l0) | ((uint32_t)__bfloat16_as_ushort(l1) << 16);
    uint32_t pl1 = (uint32_t)__bfloat16_as_ushort(l2) | ((uint32_t)__bfloat16_as_ushort(l3) << 16);
    *reinterpret_cast<uint2*>(g_nf_hi + 4 * (size_t)id) = make_uint2(ph0, ph1);
    *reinterpret_cast<uint2*>(g_nf_lo + 4 * (size_t)id) = make_uint2(pl0, pl1);
}

template<int WHICH>
__global__ void transpose_split_kernel(const float* __restrict__ W)
{
    constexpr int K = (WHICH == 1) ? 2 * DNODE : DHID;
    constexpr int KSHIFT = (WHICH == 1) ? 11 : 10;
    __nv_bfloat16* hi = (WHICH == 1) ? g_W1T_hi : g_W2T_hi;
    __nv_bfloat16* lo = (WHICH == 1) ? g_W1T_lo : g_W2T_lo;
    size_t id = (size_t)blockIdx.x * blockDim.x + threadIdx.x;
    if (id >= (size_t)K * DHID) return;
    int k = (int)(id & (size_t)(K - 1));
    int n = (int)(id >> KSHIFT);
    float x = W[(size_t)k * DHID + n];
    __nv_bfloat16 h, l;
    split1(x, h, l);
    hi[id] = h;
    lo[id] = l;
}

// ---------------------------------------------------------------------------
// Split-bf16 raw-MMA GEMM v6.
//   BM=128, BN=128, BK=32; 8 warps (4m x 2n), warp tile 32x64.
//   Inner loop: ldmatrix.x4 + mma.sync.m16n8k16 with precomputed smem
//   addresses (kills wmma's per-fragment address recomputation overhead).
//   cp.async double-buffered, one barrier per k-tile, 2 CTAs/SM.
// ---------------------------------------------------------------------------
static constexpr int RSB  = 80;                 // smem row stride bytes (40 bf16)
static constexpr int MBUF = 128 * RSB;          // 10240 B: one matrix buffer
static constexpr int SBUF = 4 * MBUF;           // 40960 B: Ah|Al|Bh|Bl
static constexpr int HDR  = 1536;               // s_src 512 | s_dst 512 | s_bias 512
static constexpr int SMEM_BYTES = HDR + 2 * SBUF;   // 83456

template<int KTOT, bool STAGE1>
__global__ __launch_bounds__(256, 2)
void gemm_kernel(const int* __restrict__ src, const int* __restrict__ dst,
                 const float* __restrict__ bias, float* __restrict__ out)
{
    extern __shared__ char smem[];
    int*   s_src  = (int*)smem;
    int*   s_dst  = (int*)(smem + 512);
    float* s_bias = (float*)(smem + 1024);
    char*  tiles  = smem + HDR;
    const uint32_t tiles_u32 = smem_u32(tiles);

    const int tid  = threadIdx.x;
    const int lane = tid & 31;
    const int wid  = tid >> 5;
    const int wm   = wid & 3;      // 4 warps along M (32 rows each)
    const int wn   = wid >> 2;     // 2 warps along N (64 cols each)
    const int m0 = blockIdx.y * 128;
    const int n0 = blockIdx.x * 128;

    if (tid < 128) {
        if (STAGE1) {
            s_src[tid] = src[m0 + tid];
            s_dst[tid] = dst[m0 + tid];
        }
        s_bias[tid] = bias[n0 + tid];
    }
    __syncthreads();

    const __nv_bfloat16* Ahi = STAGE1 ? g_nf_hi : g_H_hi;
    const __nv_bfloat16* Alo = STAGE1 ? g_nf_lo : g_H_lo;
    const __nv_bfloat16* Bhi = STAGE1 ? g_W1T_hi : g_W2T_hi;
    const __nv_bfloat16* Blo = STAGE1 ? g_W1T_lo : g_W2T_lo;

    constexpr int NT = KTOT / 32;

    // acc[mi][n8][4]: mi = m16 block (2), n8 = n8 block (8)
    float acc[2][8][4];
    #pragma unroll
    for (int i = 0; i < 2; ++i)
        #pragma unroll
        for (int j = 0; j < 8; ++j)
            #pragma unroll
            for (int q = 0; q < 4; ++q) acc[i][j][q] = 0.0f;

    // Precomputed per-warp ldmatrix base addresses (buffer 0).
    const int lrow = lane & 15;
    const int lkb  = (lane >> 4) * 16;   // k-byte half within k16 step
    const uint32_t aBase = tiles_u32 + (wm * 32 + lrow) * RSB + lkb;            // Ah
    const uint32_t bBase = tiles_u32 + 2 * MBUF + (wn * 64 + lrow) * RSB + lkb; // Bh

    // cp.async one k-tile into stage s. 256 threads: thread t -> row t/2,
    // 32B half (t&1) of the 64B row, for Ah/Al/Bh/Bl (8 x 16B chunks).
    auto issue_tile = [&](int kt, int s) {
        const int kglob = kt * 32;
        const int row  = tid >> 1;
        const int half = (tid & 1) * 16;   // bf16 elem offset within 32-elem row
        const uint32_t base = tiles_u32 + s * SBUF + row * RSB + half * 2;
        size_t gA;
        if (STAGE1) {
            const int* sidx = (kglob < DNODE) ? s_src : s_dst;
            gA = ((size_t)sidx[row] << 10) + (kglob & (DNODE - 1)) + half;
        } else {
            gA = ((size_t)(m0 + row) << 10) + kglob + half;
        }
        const size_t gB = (size_t)(n0 + row) * KTOT + kglob + half;
        #pragma unroll
        for (int ch = 0; ch < 2; ++ch) {
            cp16(base + 0 * MBUF + ch * 16, Ahi + gA + ch * 8);
            cp16(base + 1 * MBUF + ch * 16, Alo + gA + ch * 8);
            cp16(base + 2 * MBUF + ch * 16, Bhi + gB + ch * 8);
            cp16(base + 3 * MBUF + ch * 16, Blo + gB + ch * 8);
        }
    };

    auto compute = [&](int s) {
        const uint32_t aB = aBase + s * SBUF;   // Ah base this buffer
        const uint32_t bB = bBase + s * SBUF;   // Bh base this buffer
        #pragma unroll
        for (int kk = 0; kk < 2; ++kk) {
            const uint32_t cb = kk * 32;        // k-byte offset of this k16 step
            uint32_t ah[2][4], al[2][4], b[4][4];
            // A fragments (hi & lo), 16 rows per block, blocks 16 rows apart
            ldsm4(ah[0], aB + cb);
            ldsm4(ah[1], aB + 16 * RSB + cb);
            ldsm4(al[0], aB + MBUF + cb);
            ldsm4(al[1], aB + MBUF + 16 * RSB + cb);
            // B hi fragments: 4 n16 blocks
            #pragma unroll
            for (int j = 0; j < 4; ++j)
                ldsm4(b[j], bB + j * 16 * RSB + cb);
            // term 1: Ah * Bh
            #pragma unroll
            for (int mi = 0; mi < 2; ++mi)
                #pragma unroll
                for (int j = 0; j < 4; ++j)
                    #pragma unroll
                    for (int s2 = 0; s2 < 2; ++s2)
                        mma16816(acc[mi][j * 2 + s2], ah[mi], b[j][s2], b[j][s2 + 2]);
            // term 2: Al * Bh
            #pragma unroll
            for (int mi = 0; mi < 2; ++mi)
                #pragma unroll
                for (int j = 0; j < 4; ++j)
                    #pragma unroll
                    for (int s2 = 0; s2 < 2; ++s2)
                        mma16816(acc[mi][j * 2 + s2], al[mi], b[j][s2], b[j][s2 + 2]);
            // reload B as lo, term 3: Ah * Bl
            #pragma unroll
            for (int j = 0; j < 4; ++j)
                ldsm4(b[j], bB + MBUF + j * 16 * RSB + cb);
            #pragma unroll
            for (int mi = 0; mi < 2; ++mi)
                #pragma unroll
                for (int j = 0; j < 4; ++j)
                    #pragma unroll
                    for (int s2 = 0; s2 < 2; ++s2)
                        mma16816(acc[mi][j * 2 + s2], ah[mi], b[j][s2], b[j][s2 + 2]);
        }
    };

    issue_tile(0, 0);
    cp_commit();
    for (int kt = 0; kt < NT; ++kt) {
        cp_wait<0>();        // tile kt landed
        __syncthreads();     // publish tile kt; order compute(kt-1) before overwrite
        if (kt + 1 < NT) {
            issue_tile(kt + 1, (kt + 1) & 1);   // in flight during compute(kt)
            cp_commit();
        }
        compute(kt & 1);
    }

    // ---- direct register epilogue (documented m16n8 acc layout) ----
    const int grp = lane >> 2, tg = lane & 3;
    #pragma unroll
    for (int mi = 0; mi < 2; ++mi) {
        const int rbase = m0 + wm * 32 + mi * 16 + grp;
        #pragma unroll
        for (int n8 = 0; n8 < 8; ++n8) {
            const float* c = acc[mi][n8];
            const int colL = wn * 64 + n8 * 8 + tg * 2;
            const int col  = n0 + colL;
            const float b0 = s_bias[colL], b1 = s_bias[colL + 1];
            #pragma unroll
            for (int half = 0; half < 2; ++half) {
                const int r = rbase + half * 8;
                float v0 = c[half * 2 + 0] + b0;
                float v1 = c[half * 2 + 1] + b1;
                if (STAGE1) {
                    v0 = v0 > 0.0f ? v0 : 0.0f;
                    v1 = v1 > 0.0f ? v1 : 0.0f;
                    __nv_bfloat16 h0, h1, l0, l1;
                    split1(v0, h0, l0);
                    split1(v1, h1, l1);
                    const uint32_t ph = (uint32_t)__bfloat16_as_ushort(h0) |
                                        ((uint32_t)__bfloat16_as_ushort(h1) << 16);
                    const uint32_t pl = (uint32_t)__bfloat16_as_ushort(l0) |
                                        ((uint32_t)__bfloat16_as_ushort(l1) << 16);
                    const size_t o = ((size_t)r << 10) + col;
                    *reinterpret_cast<uint32_t*>(g_H_hi + o) = ph;
                    *reinterpret_cast<uint32_t*>(g_H_lo + o) = pl;
                } else {
                    *reinterpret_cast<float2*>(out + ((size_t)r << 10) + col) =
                        make_float2(v0, v1);
                }
            }
        }
    }
}

// ---------------------------------------------------------------------------
extern "C" void kernel_launch(void* const* d_in, const int* in_sizes, int n_in,
                              void* d_out, int out_size)
{
    const float* nf  = (const float*)d_in[0];
    const int*   src = (const int*)d_in[1];   // JAX int64 downcasts to int32 (x64 off)
    const int*   dst = (const int*)d_in[2];
    const float* W1  = (const float*)d_in[3];
    const float* b1  = (const float*)d_in[4];
    const float* W2  = (const float*)d_in[5];
    const float* b2  = (const float*)d_in[6];
    float*       out = (float*)d_out;

    cudaFuncSetAttribute(gemm_kernel<2 * DNODE, true>,
                         cudaFuncAttributeMaxDynamicSharedMemorySize, SMEM_BYTES);
    cudaFuncSetAttribute(gemm_kernel<DHID, false>,
                         cudaFuncAttributeMaxDynamicSharedMemorySize, SMEM_BYTES);

    // 1) split node features into bf16 hi/lo
    {
        int n4 = (NNODES * DNODE) / 4;
        split_nf_kernel<<<(n4 + 255) / 256, 256>>>((const float4*)nf, n4);
    }
    // 2) transpose+split weights
    {
        size_t t1 = (size_t)(2 * DNODE) * DHID;
        transpose_split_kernel<1><<<(unsigned)((t1 + 255) / 256), 256>>>(W1);
        size_t t2 = (size_t)DHID * DHID;
        transpose_split_kernel<2><<<(unsigned)((t2 + 255) / 256), 256>>>(W2);
    }
    // 3) stage 1: H = relu(concat @ W1 + b1)  (K = 2048)
    {
        dim3 grid(DHID / 128, NEDGES / 128);
        gemm_kernel<2 * DNODE, true><<<grid, 256, SMEM_BYTES>>>(src, dst, b1, nullptr);
    }
    // 4) stage 2: out = H @ W2 + b2  (K = 1024)
    {
        dim3 grid(DHID / 128, NEDGES / 128);
        gemm_kernel<DHID, false><<<grid, 256, SMEM_BYTES>>>(src, dst, b2, out);
    }
}

// round 13
// speedup vs baseline: 1.1651x; 1.1429x over previous
#include <cuda_runtime.h>
#include <cuda_bf16.h>
#include <cstdint>

#define NEDGES 65536
#define NNODES 50000
#define NPAD   50048          // 391 * 128
#define DNODE  1024
#define DHID   1024

// ---------------------------------------------------------------------------
// Device scratch (static). Referenced ONLY from device code — passing a
// __device__ array as a kernel argument from host passes the host shadow
// address (GB300/ATS silently writes host memory!).
// ---------------------------------------------------------------------------
__device__ __nv_bfloat16 g_nf_hi[(size_t)NNODES * DNODE];
__device__ __nv_bfloat16 g_nf_lo[(size_t)NNODES * DNODE];
__device__ __nv_bfloat16 g_W1T_hi[(size_t)(2 * DNODE) * DHID];   // [N'=2048][K=1024]
__device__ __nv_bfloat16 g_W1T_lo[(size_t)(2 * DNODE) * DHID];
__device__ __nv_bfloat16 g_W2T_hi[(size_t)DHID * DHID];          // [N=1024][K=1024]
__device__ __nv_bfloat16 g_W2T_lo[(size_t)DHID * DHID];
__device__ float         g_P[(size_t)NPAD * (2 * DNODE)];        // U|V  [NPAD][2048]
__device__ __nv_bfloat16 g_H_hi[(size_t)NEDGES * DHID];
__device__ __nv_bfloat16 g_H_lo[(size_t)NEDGES * DHID];

__device__ __forceinline__ void split1(float x, __nv_bfloat16& h, __nv_bfloat16& l) {
    h = __float2bfloat16(x);
    l = __float2bfloat16(x - __bfloat162float(h));
}

__device__ __forceinline__ uint32_t smem_u32(const void* p) {
    uint32_t a;
    asm("{ .reg .u64 t; cvta.to.shared.u64 t, %1; cvt.u32.u64 %0, t; }" : "=r"(a) : "l"(p));
    return a;
}
__device__ __forceinline__ void cp16(uint32_t saddr, const void* g) {
    asm volatile("cp.async.cg.shared.global [%0], [%1], 16;" :: "r"(saddr), "l"(g));
}
__device__ __forceinline__ void cp_commit() {
    asm volatile("cp.async.commit_group;");
}
template<int N>
__device__ __forceinline__ void cp_wait() {
    asm volatile("cp.async.wait_group %0;" :: "n"(N));
}
__device__ __forceinline__ void ldsm4(uint32_t* r, uint32_t addr) {
    asm volatile("ldmatrix.sync.aligned.m8n8.x4.shared.b16 {%0,%1,%2,%3}, [%4];"
                 : "=r"(r[0]), "=r"(r[1]), "=r"(r[2]), "=r"(r[3]) : "r"(addr));
}
__device__ __forceinline__ void mma16816(float* c, const uint32_t* a,
                                         uint32_t b0, uint32_t b1) {
    asm volatile(
        "mma.sync.aligned.m16n8k16.row.col.f32.bf16.bf16.f32 "
        "{%0,%1,%2,%3}, {%4,%5,%6,%7}, {%8,%9}, {%0,%1,%2,%3};"
        : "+f"(c[0]), "+f"(c[1]), "+f"(c[2]), "+f"(c[3])
        : "r"(a[0]), "r"(a[1]), "r"(a[2]), "r"(a[3]), "r"(b0), "r"(b1));
}

// ---------------------------------------------------------------------------
// Pre-pass kernels (globals written device-side)
// ---------------------------------------------------------------------------
__global__ void split_nf_kernel(const float4* __restrict__ in, int n4)
{
    int id = blockIdx.x * blockDim.x + threadIdx.x;
    if (id >= n4) return;
    float4 v = in[id];
    __nv_bfloat16 h0, h1, h2, h3, l0, l1, l2, l3;
    split1(v.x, h0, l0); split1(v.y, h1, l1);
    split1(v.z, h2, l2); split1(v.w, h3, l3);
    uint32_t ph0 = (uint32_t)__bfloat16_as_ushort(h0) | ((uint32_t)__bfloat16_as_ushort(h1) << 16);
    uint32_t ph1 = (uint32_t)__bfloat16_as_ushort(h2) | ((uint32_t)__bfloat16_as_ushort(h3) << 16);
    uint32_t pl0 = (uint32_t)__bfloat16_as_ushort(l0) | ((uint32_t)__bfloat16_as_ushort(l1) << 16);
    uint32_t pl1 = (uint32_t)__bfloat16_as_ushort(l2) | ((uint32_t)__bfloat16_as_ushort(l3) << 16);
    *reinterpret_cast<uint2*>(g_nf_hi + 4 * (size_t)id) = make_uint2(ph0, ph1);
    *reinterpret_cast<uint2*>(g_nf_lo + 4 * (size_t)id) = make_uint2(pl0, pl1);
}

// W1 [2048,1024] -> B' [n'=2048][k=1024]:
//   n'<1024:  B'[n',k] = W1[k,        n']        (U = nf @ W1_top)
//   n'>=1024: B'[n',k] = W1[k+1024,   n'-1024]   (V = nf @ W1_bot)
__global__ void transpose_split_W1(const float* __restrict__ W1)
{
    size_t id = (size_t)blockIdx.x * blockDim.x + threadIdx.x;
    if (id >= (size_t)(2 * DNODE) * DHID) return;
    int n = (int)(id >> 10);          // 0..2047
    int k = (int)(id & 1023);
    int srow = (n < DHID) ? k : (k + DNODE);
    int scol = n & (DHID - 1);
    float x = W1[(size_t)srow * DHID + scol];
    __nv_bfloat16 h, l;
    split1(x, h, l);
    g_W1T_hi[id] = h;
    g_W1T_lo[id] = l;
}

// W2 [1024,1024] -> W2T [N][K]
__global__ void transpose_split_W2(const float* __restrict__ W2)
{
    size_t id = (size_t)blockIdx.x * blockDim.x + threadIdx.x;
    if (id >= (size_t)DHID * DHID) return;
    int k = (int)(id & 1023);
    int n = (int)(id >> 10);
    float x = W2[(size_t)k * DHID + n];
    __nv_bfloat16 h, l;
    split1(x, h, l);
    g_W2T_hi[id] = h;
    g_W2T_lo[id] = l;
}

// Combine: H[e,:] = relu(U[src[e],:] + V[dst[e],:] + b1), split -> g_H hi/lo.
// One block per edge, 256 threads x float4.
__global__ __launch_bounds__(256)
void combine_kernel(const int* __restrict__ src, const int* __restrict__ dst,
                    const float* __restrict__ b1)
{
    const int e = blockIdx.x;
    const int t = threadIdx.x;
    const int s = src[e], d = dst[e];
    const float4 u = *reinterpret_cast<const float4*>(g_P + (size_t)s * 2048 + t * 4);
    const float4 v = *reinterpret_cast<const float4*>(g_P + (size_t)d * 2048 + 1024 + t * 4);
    const float4 bb = reinterpret_cast<const float4*>(b1)[t];
    float w[4] = {u.x + v.x + bb.x, u.y + v.y + bb.y,
                  u.z + v.z + bb.z, u.w + v.w + bb.w};
    uint32_t ph[2], pl[2];
    #pragma unroll
    for (int j = 0; j < 4; j += 2) {
        float v0 = w[j] > 0.0f ? w[j] : 0.0f;
        float v1 = w[j + 1] > 0.0f ? w[j + 1] : 0.0f;
        __nv_bfloat16 h0, h1, l0, l1;
        split1(v0, h0, l0);
        split1(v1, h1, l1);
        ph[j >> 1] = (uint32_t)__bfloat16_as_ushort(h0) | ((uint32_t)__bfloat16_as_ushort(h1) << 16);
        pl[j >> 1] = (uint32_t)__bfloat16_as_ushort(l0) | ((uint32_t)__bfloat16_as_ushort(l1) << 16);
    }
    const size_t o = ((size_t)e << 10) + t * 4;
    *reinterpret_cast<uint2*>(g_H_hi + o) = make_uint2(ph[0], ph[1]);
    *reinterpret_cast<uint2*>(g_H_lo + o) = make_uint2(pl[0], pl[1]);
}

// ---------------------------------------------------------------------------
// Split-bf16 raw-MMA GEMM (v6 inner loop). BM=128, BN=128, BK=32; K=1024.
//   MODE 0 (node): A = g_nf rows (clamped at NNODES), B = g_W1T (N-stride 1024),
//                  out = g_P fp32 (row stride 2048), no bias/relu.
//   MODE 1 (stage2): A = g_H rows, B = g_W2T, out = param (stride 1024) + bias.
// ---------------------------------------------------------------------------
static constexpr int RSB  = 80;                 // smem row stride bytes (40 bf16)
static constexpr int MBUF = 128 * RSB;          // 10240 B: one matrix buffer
static constexpr int SBUF = 4 * MBUF;           // 40960 B: Ah|Al|Bh|Bl
static constexpr int HDR  = 1024;               // s_bias
static constexpr int SMEM_BYTES = HDR + 2 * SBUF;   // 82944

template<int MODE>
__global__ __launch_bounds__(256, 2)
void gemm_kernel(const float* __restrict__ bias, float* __restrict__ out)
{
    extern __shared__ char smem[];
    float* s_bias = (float*)smem;
    char*  tiles  = smem + HDR;
    const uint32_t tiles_u32 = smem_u32(tiles);

    const int tid  = threadIdx.x;
    const int lane = tid & 31;
    const int wid  = tid >> 5;
    const int wm   = wid & 3;      // 4 warps along M (32 rows each)
    const int wn   = wid >> 2;     // 2 warps along N (64 cols each)
    const int m0 = blockIdx.y * 128;
    const int n0 = blockIdx.x * 128;

    if (MODE == 1 && tid < 128) s_bias[tid] = bias[n0 + tid];
    __syncthreads();

    const __nv_bfloat16* Ahi = (MODE == 0) ? g_nf_hi : g_H_hi;
    const __nv_bfloat16* Alo = (MODE == 0) ? g_nf_lo : g_H_lo;
    const __nv_bfloat16* Bhi = (MODE == 0) ? g_W1T_hi : g_W2T_hi;
    const __nv_bfloat16* Blo = (MODE == 0) ? g_W1T_lo : g_W2T_lo;

    constexpr int NT = 32;   // K = 1024, BK = 32

    float acc[2][8][4];
    #pragma unroll
    for (int i = 0; i < 2; ++i)
        #pragma unroll
        for (int j = 0; j < 8; ++j)
            #pragma unroll
            for (int q = 0; q < 4; ++q) acc[i][j][q] = 0.0f;

    const int lrow = lane & 15;
    const int lkb  = (lane >> 4) * 16;
    const uint32_t aBase = tiles_u32 + (wm * 32 + lrow) * RSB + lkb;
    const uint32_t bBase = tiles_u32 + 2 * MBUF + (wn * 64 + lrow) * RSB + lkb;

    // A row index for loads (clamped for the padded node tail)
    const int arow_l = tid >> 1;
    int arow_g = m0 + arow_l;
    if (MODE == 0 && arow_g >= NNODES) arow_g = 0;   // padding rows: load row 0

    auto issue_tile = [&](int kt, int s) {
        const int kglob = kt * 32;
        const int half = (tid & 1) * 16;
        const uint32_t base = tiles_u32 + s * SBUF + arow_l * RSB + half * 2;
        const size_t gA = ((size_t)arow_g << 10) + kglob + half;
        const size_t gB = (size_t)(n0 + arow_l) * 1024 + kglob + half;
        #pragma unroll
        for (int ch = 0; ch < 2; ++ch) {
            cp16(base + 0 * MBUF + ch * 16, Ahi + gA + ch * 8);
            cp16(base + 1 * MBUF + ch * 16, Alo + gA + ch * 8);
            cp16(base + 2 * MBUF + ch * 16, Bhi + gB + ch * 8);
            cp16(base + 3 * MBUF + ch * 16, Blo + gB + ch * 8);
        }
    };

    auto compute = [&](int s) {
        const uint32_t aB = aBase + s * SBUF;
        const uint32_t bB = bBase + s * SBUF;
        #pragma unroll
        for (int kk = 0; kk < 2; ++kk) {
            const uint32_t cb = kk * 32;
            uint32_t ah[2][4], al[2][4], b[4][4];
            ldsm4(ah[0], aB + cb);
            ldsm4(ah[1], aB + 16 * RSB + cb);
            ldsm4(al[0], aB + MBUF + cb);
            ldsm4(al[1], aB + MBUF + 16 * RSB + cb);
            #pragma unroll
            for (int j = 0; j < 4; ++j)
                ldsm4(b[j], bB + j * 16 * RSB + cb);
            #pragma unroll
            for (int mi = 0; mi < 2; ++mi)
                #pragma unroll
                for (int j = 0; j < 4; ++j)
                    #pragma unroll
                    for (int s2 = 0; s2 < 2; ++s2)
                        mma16816(acc[mi][j * 2 + s2], ah[mi], b[j][s2], b[j][s2 + 2]);
            #pragma unroll
            for (int mi = 0; mi < 2; ++mi)
                #pragma unroll
                for (int j = 0; j < 4; ++j)
                    #pragma unroll
                    for (int s2 = 0; s2 < 2; ++s2)
                        mma16816(acc[mi][j * 2 + s2], al[mi], b[j][s2], b[j][s2 + 2]);
            #pragma unroll
            for (int j = 0; j < 4; ++j)
                ldsm4(b[j], bB + MBUF + j * 16 * RSB + cb);
            #pragma unroll
            for (int mi = 0; mi < 2; ++mi)
                #pragma unroll
                for (int j = 0; j < 4; ++j)
                    #pragma unroll
                    for (int s2 = 0; s2 < 2; ++s2)
                        mma16816(acc[mi][j * 2 + s2], ah[mi], b[j][s2], b[j][s2 + 2]);
        }
    };

    issue_tile(0, 0);
    cp_commit();
    for (int kt = 0; kt < NT; ++kt) {
        cp_wait<0>();
        __syncthreads();
        if (kt + 1 < NT) {
            issue_tile(kt + 1, (kt + 1) & 1);
            cp_commit();
        }
        compute(kt & 1);
    }

    // ---- direct register epilogue ----
    const int grp = lane >> 2, tg = lane & 3;
    #pragma unroll
    for (int mi = 0; mi < 2; ++mi) {
        const int rbase = m0 + wm * 32 + mi * 16 + grp;
        #pragma unroll
        for (int n8 = 0; n8 < 8; ++n8) {
            const float* c = acc[mi][n8];
            const int colL = wn * 64 + n8 * 8 + tg * 2;
            const int col  = n0 + colL;
            #pragma unroll
            for (int half = 0; half < 2; ++half) {
                const int r = rbase + half * 8;
                if (MODE == 0) {
                    // P row stride 2048, fp32, no bias
                    *reinterpret_cast<float2*>(g_P + (size_t)r * 2048 + col) =
                        make_float2(c[half * 2 + 0], c[half * 2 + 1]);
                } else {
                    const float b0 = s_bias[colL], b1v = s_bias[colL + 1];
                    *reinterpret_cast<float2*>(out + ((size_t)r << 10) + col) =
                        make_float2(c[half * 2 + 0] + b0, c[half * 2 + 1] + b1v);
                }
            }
        }
    }
}

// ---------------------------------------------------------------------------
extern "C" void kernel_launch(void* const* d_in, const int* in_sizes, int n_in,
                              void* d_out, int out_size)
{
    const float* nf  = (const float*)d_in[0];
    const int*   src = (const int*)d_in[1];   // JAX int64 downcasts to int32 (x64 off)
    const int*   dst = (const int*)d_in[2];
    const float* W1  = (const float*)d_in[3];
    const float* b1  = (const float*)d_in[4];
    const float* W2  = (const float*)d_in[5];
    const float* b2  = (const float*)d_in[6];
    float*       out = (float*)d_out;

    cudaFuncSetAttribute(gemm_kernel<0>,
                         cudaFuncAttributeMaxDynamicSharedMemorySize, SMEM_BYTES);
    cudaFuncSetAttribute(gemm_kernel<1>,
                         cudaFuncAttributeMaxDynamicSharedMemorySize, SMEM_BYTES);

    // 1) split node features into bf16 hi/lo
    {
        int n4 = (NNODES * DNODE) / 4;
        split_nf_kernel<<<(n4 + 255) / 256, 256>>>((const float4*)nf, n4);
    }
    // 2) transpose+split weights
    {
        size_t t1 = (size_t)(2 * DNODE) * DHID;
        transpose_split_W1<<<(unsigned)((t1 + 255) / 256), 256>>>(W1);
        size_t t2 = (size_t)DHID * DHID;
        transpose_split_W2<<<(unsigned)((t2 + 255) / 256), 256>>>(W2);
    }
    // 3) node GEMM: P = nf @ [W1_top | W1_bot]   (M=50048, N=2048, K=1024)
    {
        dim3 grid(2 * DNODE / 128, NPAD / 128);   // (16, 391)
        gemm_kernel<0><<<grid, 256, SMEM_BYTES>>>(nullptr, nullptr);
    }
    // 4) combine: H = relu(U[src] + V[dst] + b1), split -> g_H hi/lo
    {
        combine_kernel<<<NEDGES, 256>>>(src, dst, b1);
    }
    // 5) stage 2: out = H @ W2 + b2   (M=65536, N=1024, K=1024)
    {
        dim3 grid(DHID / 128, NEDGES / 128);      // (8, 512)
        gemm_kernel<1><<<grid, 256, SMEM_BYTES>>>(b2, out);
    }
}

// round 14
// speedup vs baseline: 1.6679x; 1.4315x over previous
#include <cuda_runtime.h>
#include <cuda_fp16.h>
#include <cstdint>

#define NEDGES 65536
#define NNODES 50000
#define NPAD   50048          // 391 * 128
#define DNODE  1024
#define DHID   1024

// ---------------------------------------------------------------------------
// Device scratch (static). Referenced ONLY from device code — passing a
// __device__ array as a kernel argument from host passes the host shadow
// address (GB300/ATS silently writes host memory!).
// ---------------------------------------------------------------------------
__device__ __half g_nf[(size_t)NNODES * DNODE];                 // fp16 single
__device__ __half g_W1T_hi[(size_t)(2 * DNODE) * DHID];         // [N'=2048][K=1024]
__device__ __half g_W1T_lo[(size_t)(2 * DNODE) * DHID];
__device__ __half g_W2T_hi[(size_t)DHID * DHID];                // [N=1024][K=1024]
__device__ __half g_W2T_lo[(size_t)DHID * DHID];
__device__ float  g_P[(size_t)NPAD * (2 * DNODE)];              // U|V  [NPAD][2048]
__device__ __half g_H[(size_t)NEDGES * DHID];                   // fp16 single

__device__ __forceinline__ uint32_t smem_u32(const void* p) {
    uint32_t a;
    asm("{ .reg .u64 t; cvta.to.shared.u64 t, %1; cvt.u32.u64 %0, t; }" : "=r"(a) : "l"(p));
    return a;
}
__device__ __forceinline__ void cp16(uint32_t saddr, const void* g) {
    asm volatile("cp.async.cg.shared.global [%0], [%1], 16;" :: "r"(saddr), "l"(g));
}
__device__ __forceinline__ void cp_commit() {
    asm volatile("cp.async.commit_group;");
}
template<int N>
__device__ __forceinline__ void cp_wait() {
    asm volatile("cp.async.wait_group %0;" :: "n"(N));
}
__device__ __forceinline__ void ldsm4(uint32_t* r, uint32_t addr) {
    asm volatile("ldmatrix.sync.aligned.m8n8.x4.shared.b16 {%0,%1,%2,%3}, [%4];"
                 : "=r"(r[0]), "=r"(r[1]), "=r"(r[2]), "=r"(r[3]) : "r"(addr));
}
__device__ __forceinline__ void mma16816(float* c, const uint32_t* a,
                                         uint32_t b0, uint32_t b1) {
    asm volatile(
        "mma.sync.aligned.m16n8k16.row.col.f32.f16.f16.f32 "
        "{%0,%1,%2,%3}, {%4,%5,%6,%7}, {%8,%9}, {%0,%1,%2,%3};"
        : "+f"(c[0]), "+f"(c[1]), "+f"(c[2]), "+f"(c[3])
        : "r"(a[0]), "r"(a[1]), "r"(a[2]), "r"(a[3]), "r"(b0), "r"(b1));
}

// ---------------------------------------------------------------------------
// Pre-pass kernels (globals written device-side)
// ---------------------------------------------------------------------------
__global__ void conv_nf_kernel(const float4* __restrict__ in, int n4)
{
    int id = blockIdx.x * blockDim.x + threadIdx.x;
    if (id >= n4) return;
    float4 v = in[id];
    __half2 p0 = __floats2half2_rn(v.x, v.y);
    __half2 p1 = __floats2half2_rn(v.z, v.w);
    *reinterpret_cast<uint2*>(g_nf + 4 * (size_t)id) =
        make_uint2(*reinterpret_cast<uint32_t*>(&p0), *reinterpret_cast<uint32_t*>(&p1));
}

// W1 [2048,1024] -> B' [n'=2048][k=1024] fp16 hi/lo split:
//   n'<1024:  B'[n',k] = W1[k,      n']        (U = nf @ W1_top)
//   n'>=1024: B'[n',k] = W1[k+1024, n'-1024]   (V = nf @ W1_bot)
__global__ void transpose_split_W1(const float* __restrict__ W1)
{
    size_t id = (size_t)blockIdx.x * blockDim.x + threadIdx.x;
    if (id >= (size_t)(2 * DNODE) * DHID) return;
    int n = (int)(id >> 10);          // 0..2047
    int k = (int)(id & 1023);
    int srow = (n < DHID) ? k : (k + DNODE);
    int scol = n & (DHID - 1);
    float x = W1[(size_t)srow * DHID + scol];
    __half h = __float2half_rn(x);
    g_W1T_hi[id] = h;
    g_W1T_lo[id] = __float2half_rn(x - __half2float(h));
}

// W2 [1024,1024] -> W2T [N][K] fp16 hi/lo split
__global__ void transpose_split_W2(const float* __restrict__ W2)
{
    size_t id = (size_t)blockIdx.x * blockDim.x + threadIdx.x;
    if (id >= (size_t)DHID * DHID) return;
    int k = (int)(id & 1023);
    int n = (int)(id >> 10);
    float x = W2[(size_t)k * DHID + n];
    __half h = __float2half_rn(x);
    g_W2T_hi[id] = h;
    g_W2T_lo[id] = __float2half_rn(x - __half2float(h));
}

// Combine: H[e,:] = relu(U[src[e],:] + V[dst[e],:] + b1) -> fp16 g_H.
// One block per edge, 256 threads x float4.
__global__ __launch_bounds__(256)
void combine_kernel(const int* __restrict__ src, const int* __restrict__ dst,
                    const float* __restrict__ b1)
{
    const int e = blockIdx.x;
    const int t = threadIdx.x;
    const int s = src[e], d = dst[e];
    const float4 u = *reinterpret_cast<const float4*>(g_P + (size_t)s * 2048 + t * 4);
    const float4 v = *reinterpret_cast<const float4*>(g_P + (size_t)d * 2048 + 1024 + t * 4);
    const float4 bb = reinterpret_cast<const float4*>(b1)[t];
    float w0 = u.x + v.x + bb.x, w1 = u.y + v.y + bb.y;
    float w2 = u.z + v.z + bb.z, w3 = u.w + v.w + bb.w;
    w0 = w0 > 0.0f ? w0 : 0.0f;  w1 = w1 > 0.0f ? w1 : 0.0f;
    w2 = w2 > 0.0f ? w2 : 0.0f;  w3 = w3 > 0.0f ? w3 : 0.0f;
    __half2 p0 = __floats2half2_rn(w0, w1);
    __half2 p1 = __floats2half2_rn(w2, w3);
    *reinterpret_cast<uint2*>(g_H + ((size_t)e << 10) + t * 4) =
        make_uint2(*reinterpret_cast<uint32_t*>(&p0), *reinterpret_cast<uint32_t*>(&p1));
}

// ---------------------------------------------------------------------------
// 2-term fp16 raw-MMA GEMM: D = A_fp16 * (Bh + Bl), fp32 accumulate.
//   BM=128, BN=128, BK=32; 8 warps (4m x 2n), warp tile 32x64.
//   cp.async double-buffered (3 matrices: A | Bh | Bl), one barrier per k-tile.
//   MODE 0 (node): A = g_nf rows (clamped), out = g_P fp32 (stride 2048).
//   MODE 1 (stage2): A = g_H rows, out = param (stride 1024) + bias.
// ---------------------------------------------------------------------------
static constexpr int RSB  = 80;                 // smem row stride bytes (40 fp16)
static constexpr int MBUF = 128 * RSB;          // 10240 B: one matrix buffer
static constexpr int SBUF = 3 * MBUF;           // 30720 B: A|Bh|Bl
static constexpr int HDR  = 1024;               // s_bias
static constexpr int SMEM_BYTES = HDR + 2 * SBUF;   // 62464

template<int MODE>
__global__ __launch_bounds__(256, 2)
void gemm_kernel(const float* __restrict__ bias, float* __restrict__ out)
{
    extern __shared__ char smem[];
    float* s_bias = (float*)smem;
    char*  tiles  = smem + HDR;
    const uint32_t tiles_u32 = smem_u32(tiles);

    const int tid  = threadIdx.x;
    const int lane = tid & 31;
    const int wid  = tid >> 5;
    const int wm   = wid & 3;      // 4 warps along M (32 rows each)
    const int wn   = wid >> 2;     // 2 warps along N (64 cols each)
    const int m0 = blockIdx.y * 128;
    const int n0 = blockIdx.x * 128;

    if (MODE == 1 && tid < 128) s_bias[tid] = bias[n0 + tid];
    __syncthreads();

    const __half* A   = (MODE == 0) ? g_nf : g_H;
    const __half* Bhi = (MODE == 0) ? g_W1T_hi : g_W2T_hi;
    const __half* Blo = (MODE == 0) ? g_W1T_lo : g_W2T_lo;

    constexpr int NT = 32;   // K = 1024, BK = 32

    float acc[2][8][4];
    #pragma unroll
    for (int i = 0; i < 2; ++i)
        #pragma unroll
        for (int j = 0; j < 8; ++j)
            #pragma unroll
            for (int q = 0; q < 4; ++q) acc[i][j][q] = 0.0f;

    const int lrow = lane & 15;
    const int lkb  = (lane >> 4) * 16;
    const uint32_t aBase = tiles_u32 + (wm * 32 + lrow) * RSB + lkb;
    const uint32_t bBase = tiles_u32 + MBUF + (wn * 64 + lrow) * RSB + lkb;

    // A row index for loads (clamped for the padded node tail)
    const int arow_l = tid >> 1;
    int arow_g = m0 + arow_l;
    if (MODE == 0 && arow_g >= NNODES) arow_g = 0;   // padding rows: load row 0

    auto issue_tile = [&](int kt, int s) {
        const int kglob = kt * 32;
        const int half = (tid & 1) * 16;
        const uint32_t base = tiles_u32 + s * SBUF + arow_l * RSB + half * 2;
        const size_t gA = ((size_t)arow_g << 10) + kglob + half;
        const size_t gB = (size_t)(n0 + arow_l) * 1024 + kglob + half;
        #pragma unroll
        for (int ch = 0; ch < 2; ++ch) {
            cp16(base + 0 * MBUF + ch * 16, A   + gA + ch * 8);
            cp16(base + 1 * MBUF + ch * 16, Bhi + gB + ch * 8);
            cp16(base + 2 * MBUF + ch * 16, Blo + gB + ch * 8);
        }
    };

    auto compute = [&](int s) {
        const uint32_t aB = aBase + s * SBUF;
        const uint32_t bB = bBase + s * SBUF;
        #pragma unroll
        for (int kk = 0; kk < 2; ++kk) {
            const uint32_t cb = kk * 32;
            uint32_t ah[2][4], b[4][4];
            ldsm4(ah[0], aB + cb);
            ldsm4(ah[1], aB + 16 * RSB + cb);
            // B hi fragments: 4 n16 blocks
            #pragma unroll
            for (int j = 0; j < 4; ++j)
                ldsm4(b[j], bB + j * 16 * RSB + cb);
            // term 1: A * Bh
            #pragma unroll
            for (int mi = 0; mi < 2; ++mi)
                #pragma unroll
                for (int j = 0; j < 4; ++j)
                    #pragma unroll
                    for (int s2 = 0; s2 < 2; ++s2)
                        mma16816(acc[mi][j * 2 + s2], ah[mi], b[j][s2], b[j][s2 + 2]);
            // reload B as lo, term 2: A * Bl
            #pragma unroll
            for (int j = 0; j < 4; ++j)
                ldsm4(b[j], bB + MBUF + j * 16 * RSB + cb);
            #pragma unroll
            for (int mi = 0; mi < 2; ++mi)
                #pragma unroll
                for (int j = 0; j < 4; ++j)
                    #pragma unroll
                    for (int s2 = 0; s2 < 2; ++s2)
                        mma16816(acc[mi][j * 2 + s2], ah[mi], b[j][s2], b[j][s2 + 2]);
        }
    };

    issue_tile(0, 0);
    cp_commit();
    for (int kt = 0; kt < NT; ++kt) {
        cp_wait<0>();
        __syncthreads();
        if (kt + 1 < NT) {
            issue_tile(kt + 1, (kt + 1) & 1);
            cp_commit();
        }
        compute(kt & 1);
    }

    // ---- direct register epilogue ----
    const int grp = lane >> 2, tg = lane & 3;
    #pragma unroll
    for (int mi = 0; mi < 2; ++mi) {
        const int rbase = m0 + wm * 32 + mi * 16 + grp;
        #pragma unroll
        for (int n8 = 0; n8 < 8; ++n8) {
            const float* c = acc[mi][n8];
            const int colL = wn * 64 + n8 * 8 + tg * 2;
            const int col  = n0 + colL;
            #pragma unroll
            for (int half = 0; half < 2; ++half) {
                const int r = rbase + half * 8;
                if (MODE == 0) {
                    // P row stride 2048, fp32, no bias (skip padded rows)
                    if (r < NNODES)
                        *reinterpret_cast<float2*>(g_P + (size_t)r * 2048 + col) =
                            make_float2(c[half * 2 + 0], c[half * 2 + 1]);
                } else {
                    const float b0 = s_bias[colL], b1v = s_bias[colL + 1];
                    *reinterpret_cast<float2*>(out + ((size_t)r << 10) + col) =
                        make_float2(c[half * 2 + 0] + b0, c[half * 2 + 1] + b1v);
                }
            }
        }
    }
}

// ---------------------------------------------------------------------------
extern "C" void kernel_launch(void* const* d_in, const int* in_sizes, int n_in,
                              void* d_out, int out_size)
{
    const float* nf  = (const float*)d_in[0];
    const int*   src = (const int*)d_in[1];   // JAX int64 downcasts to int32 (x64 off)
    const int*   dst = (const int*)d_in[2];
    const float* W1  = (const float*)d_in[3];
    const float* b1  = (const float*)d_in[4];
    const float* W2  = (const float*)d_in[5];
    const float* b2  = (const float*)d_in[6];
    float*       out = (float*)d_out;

    cudaFuncSetAttribute(gemm_kernel<0>,
                         cudaFuncAttributeMaxDynamicSharedMemorySize, SMEM_BYTES);
    cudaFuncSetAttribute(gemm_kernel<1>,
                         cudaFuncAttributeMaxDynamicSharedMemorySize, SMEM_BYTES);

    // 1) convert node features to fp16
    {
        int n4 = (NNODES * DNODE) / 4;
        conv_nf_kernel<<<(n4 + 255) / 256, 256>>>((const float4*)nf, n4);
    }
    // 2) transpose + fp16 hi/lo split of weights
    {
        size_t t1 = (size_t)(2 * DNODE) * DHID;
        transpose_split_W1<<<(unsigned)((t1 + 255) / 256), 256>>>(W1);
        size_t t2 = (size_t)DHID * DHID;
        transpose_split_W2<<<(unsigned)((t2 + 255) / 256), 256>>>(W2);
    }
    // 3) node GEMM: P = nf @ [W1_top | W1_bot]   (M=50048, N=2048, K=1024)
    {
        dim3 grid(2 * DNODE / 128, NPAD / 128);   // (16, 391)
        gemm_kernel<0><<<grid, 256, SMEM_BYTES>>>(nullptr, nullptr);
    }
    // 4) combine: H = relu(U[src] + V[dst] + b1) -> fp16 g_H
    {
        combine_kernel<<<NEDGES, 256>>>(src, dst, b1);
    }
    // 5) stage 2: out = H @ W2 + b2   (M=65536, N=1024, K=1024)
    {
        dim3 grid(DHID / 128, NEDGES / 128);      // (8, 512)
        gemm_kernel<1><<<grid, 256, SMEM_BYTES>>>(b2, out);
    }
}

// round 15
// speedup vs baseline: 2.7567x; 1.6528x over previous
#include <cuda_runtime.h>
#include <cuda_fp16.h>
#include <cstdint>

#define NEDGES 65536
#define NNODES 50000
#define NPAD   50048          // 391 * 128
#define DNODE  1024
#define DHID   1024

// ---------------------------------------------------------------------------
// Device scratch (static). Referenced ONLY from device code — passing a
// __device__ array as a kernel argument from host passes the host shadow
// address (GB300/ATS silently writes host memory!).
// ---------------------------------------------------------------------------
__device__ __half g_nf[(size_t)NNODES * DNODE];                 // fp16
__device__ __half g_W1T[(size_t)(2 * DNODE) * DHID];            // [N'=2048][K=1024]
__device__ __half g_W2T[(size_t)DHID * DHID];                   // [N=1024][K=1024]
__device__ float  g_P[(size_t)NPAD * (2 * DNODE)];              // U|V  [NPAD][2048]
__device__ __half g_H[(size_t)NEDGES * DHID];                   // fp16

__device__ __forceinline__ uint32_t smem_u32(const void* p) {
    uint32_t a;
    asm("{ .reg .u64 t; cvta.to.shared.u64 t, %1; cvt.u32.u64 %0, t; }" : "=r"(a) : "l"(p));
    return a;
}
__device__ __forceinline__ void cp16(uint32_t saddr, const void* g) {
    asm volatile("cp.async.cg.shared.global [%0], [%1], 16;" :: "r"(saddr), "l"(g));
}
__device__ __forceinline__ void cp_commit() {
    asm volatile("cp.async.commit_group;");
}
template<int N>
__device__ __forceinline__ void cp_wait() {
    asm volatile("cp.async.wait_group %0;" :: "n"(N));
}
__device__ __forceinline__ void ldsm4(uint32_t* r, uint32_t addr) {
    asm volatile("ldmatrix.sync.aligned.m8n8.x4.shared.b16 {%0,%1,%2,%3}, [%4];"
                 : "=r"(r[0]), "=r"(r[1]), "=r"(r[2]), "=r"(r[3]) : "r"(addr));
}
__device__ __forceinline__ void mma16816(float* c, const uint32_t* a,
                                         uint32_t b0, uint32_t b1) {
    asm volatile(
        "mma.sync.aligned.m16n8k16.row.col.f32.f16.f16.f32 "
        "{%0,%1,%2,%3}, {%4,%5,%6,%7}, {%8,%9}, {%0,%1,%2,%3};"
        : "+f"(c[0]), "+f"(c[1]), "+f"(c[2]), "+f"(c[3])
        : "r"(a[0]), "r"(a[1]), "r"(a[2]), "r"(a[3]), "r"(b0), "r"(b1));
}

// ---------------------------------------------------------------------------
// Pre-pass kernels (globals written device-side)
// ---------------------------------------------------------------------------
__global__ void conv_nf_kernel(const float4* __restrict__ in, int n4)
{
    int id = blockIdx.x * blockDim.x + threadIdx.x;
    if (id >= n4) return;
    float4 v = in[id];
    __half2 p0 = __floats2half2_rn(v.x, v.y);
    __half2 p1 = __floats2half2_rn(v.z, v.w);
    *reinterpret_cast<uint2*>(g_nf + 4 * (size_t)id) =
        make_uint2(*reinterpret_cast<uint32_t*>(&p0), *reinterpret_cast<uint32_t*>(&p1));
}

// W1 [2048,1024] -> B' [n'=2048][k=1024] fp16:
//   n'<1024:  B'[n',k] = W1[k,      n']        (U = nf @ W1_top)
//   n'>=1024: B'[n',k] = W1[k+1024, n'-1024]   (V = nf @ W1_bot)
__global__ void transpose_W1(const float* __restrict__ W1)
{
    size_t id = (size_t)blockIdx.x * blockDim.x + threadIdx.x;
    if (id >= (size_t)(2 * DNODE) * DHID) return;
    int n = (int)(id >> 10);          // 0..2047
    int k = (int)(id & 1023);
    int srow = (n < DHID) ? k : (k + DNODE);
    int scol = n & (DHID - 1);
    g_W1T[id] = __float2half_rn(W1[(size_t)srow * DHID + scol]);
}

// W2 [1024,1024] -> W2T [N][K] fp16
__global__ void transpose_W2(const float* __restrict__ W2)
{
    size_t id = (size_t)blockIdx.x * blockDim.x + threadIdx.x;
    if (id >= (size_t)DHID * DHID) return;
    int k = (int)(id & 1023);
    int n = (int)(id >> 10);
    g_W2T[id] = __float2half_rn(W2[(size_t)k * DHID + n]);
}

// Combine: H[e,:] = relu(U[src[e],:] + V[dst[e],:] + b1) -> fp16 g_H.
// One block per edge, 256 threads x float4.
__global__ __launch_bounds__(256)
void combine_kernel(const int* __restrict__ src, const int* __restrict__ dst,
                    const float* __restrict__ b1)
{
    const int e = blockIdx.x;
    const int t = threadIdx.x;
    const int s = src[e], d = dst[e];
    const float4 u = *reinterpret_cast<const float4*>(g_P + (size_t)s * 2048 + t * 4);
    const float4 v = *reinterpret_cast<const float4*>(g_P + (size_t)d * 2048 + 1024 + t * 4);
    const float4 bb = reinterpret_cast<const float4*>(b1)[t];
    float w0 = u.x + v.x + bb.x, w1 = u.y + v.y + bb.y;
    float w2 = u.z + v.z + bb.z, w3 = u.w + v.w + bb.w;
    w0 = w0 > 0.0f ? w0 : 0.0f;  w1 = w1 > 0.0f ? w1 : 0.0f;
    w2 = w2 > 0.0f ? w2 : 0.0f;  w3 = w3 > 0.0f ? w3 : 0.0f;
    __half2 p0 = __floats2half2_rn(w0, w1);
    __half2 p1 = __floats2half2_rn(w2, w3);
    *reinterpret_cast<uint2*>(g_H + ((size_t)e << 10) + t * 4) =
        make_uint2(*reinterpret_cast<uint32_t*>(&p0), *reinterpret_cast<uint32_t*>(&p1));
}

// ---------------------------------------------------------------------------
// Pure fp16 raw-MMA GEMM: D = A * B, fp32 accumulate.
//   BM=128, BN=128, BK=32; 8 warps (4m x 2n), warp tile 32x64.
//   cp.async double-buffered (A | B), one barrier per k-tile, 2 CTAs/SM.
//   MODE 0 (node): A = g_nf rows (clamped), out = g_P fp32 (stride 2048).
//   MODE 1 (stage2): A = g_H rows, out = param (stride 1024) + bias.
// ---------------------------------------------------------------------------
static constexpr int RSB  = 80;                 // smem row stride bytes (40 fp16)
static constexpr int MBUF = 128 * RSB;          // 10240 B: one matrix buffer
static constexpr int SBUF = 2 * MBUF;           // 20480 B: A|B
static constexpr int HDR  = 1024;               // s_bias
static constexpr int SMEM_BYTES = HDR + 2 * SBUF;   // 41984

template<int MODE>
__global__ __launch_bounds__(256, 2)
void gemm_kernel(const float* __restrict__ bias, float* __restrict__ out)
{
    extern __shared__ char smem[];
    float* s_bias = (float*)smem;
    char*  tiles  = smem + HDR;
    const uint32_t tiles_u32 = smem_u32(tiles);

    const int tid  = threadIdx.x;
    const int lane = tid & 31;
    const int wid  = tid >> 5;
    const int wm   = wid & 3;      // 4 warps along M (32 rows each)
    const int wn   = wid >> 2;     // 2 warps along N (64 cols each)
    const int m0 = blockIdx.y * 128;
    const int n0 = blockIdx.x * 128;

    if (MODE == 1 && tid < 128) s_bias[tid] = bias[n0 + tid];
    __syncthreads();

    const __half* A = (MODE == 0) ? g_nf : g_H;
    const __half* B = (MODE == 0) ? g_W1T : g_W2T;

    constexpr int NT = 32;   // K = 1024, BK = 32

    float acc[2][8][4];
    #pragma unroll
    for (int i = 0; i < 2; ++i)
        #pragma unroll
        for (int j = 0; j < 8; ++j)
            #pragma unroll
            for (int q = 0; q < 4; ++q) acc[i][j][q] = 0.0f;

    const int lrow = lane & 15;
    const int lkb  = (lane >> 4) * 16;
    const uint32_t aBase = tiles_u32 + (wm * 32 + lrow) * RSB + lkb;
    const uint32_t bBase = tiles_u32 + MBUF + (wn * 64 + lrow) * RSB + lkb;

    // A row index for loads (clamped for the padded node tail)
    const int arow_l = tid >> 1;
    int arow_g = m0 + arow_l;
    if (MODE == 0 && arow_g >= NNODES) arow_g = 0;   // padding rows: load row 0

    auto issue_tile = [&](int kt, int s) {
        const int kglob = kt * 32;
        const int half = (tid & 1) * 16;
        const uint32_t base = tiles_u32 + s * SBUF + arow_l * RSB + half * 2;
        const size_t gA = ((size_t)arow_g << 10) + kglob + half;
        const size_t gB = (size_t)(n0 + arow_l) * 1024 + kglob + half;
        #pragma unroll
        for (int ch = 0; ch < 2; ++ch) {
            cp16(base + 0 * MBUF + ch * 16, A + gA + ch * 8);
            cp16(base + 1 * MBUF + ch * 16, B + gB + ch * 8);
        }
    };

    auto compute = [&](int s) {
        const uint32_t aB = aBase + s * SBUF;
        const uint32_t bB = bBase + s * SBUF;
        #pragma unroll
        for (int kk = 0; kk < 2; ++kk) {
            const uint32_t cb = kk * 32;
            uint32_t ah[2][4], b[4][4];
            ldsm4(ah[0], aB + cb);
            ldsm4(ah[1], aB + 16 * RSB + cb);
            #pragma unroll
            for (int j = 0; j < 4; ++j)
                ldsm4(b[j], bB + j * 16 * RSB + cb);
            #pragma unroll
            for (int mi = 0; mi < 2; ++mi)
                #pragma unroll
                for (int j = 0; j < 4; ++j)
                    #pragma unroll
                    for (int s2 = 0; s2 < 2; ++s2)
                        mma16816(acc[mi][j * 2 + s2], ah[mi], b[j][s2], b[j][s2 + 2]);
        }
    };

    issue_tile(0, 0);
    cp_commit();
    for (int kt = 0; kt < NT; ++kt) {
        cp_wait<0>();
        __syncthreads();
        if (kt + 1 < NT) {
            issue_tile(kt + 1, (kt + 1) & 1);
            cp_commit();
        }
        compute(kt & 1);
    }

    // ---- direct register epilogue ----
    const int grp = lane >> 2, tg = lane & 3;
    #pragma unroll
    for (int mi = 0; mi < 2; ++mi) {
        const int rbase = m0 + wm * 32 + mi * 16 + grp;
        #pragma unroll
        for (int n8 = 0; n8 < 8; ++n8) {
            const float* c = acc[mi][n8];
            const int colL = wn * 64 + n8 * 8 + tg * 2;
            const int col  = n0 + colL;
            #pragma unroll
            for (int half = 0; half < 2; ++half) {
                const int r = rbase + half * 8;
                if (MODE == 0) {
                    // P row stride 2048, fp32, no bias (skip padded rows)
                    if (r < NNODES)
                        *reinterpret_cast<float2*>(g_P + (size_t)r * 2048 + col) =
                            make_float2(c[half * 2 + 0], c[half * 2 + 1]);
                } else {
                    const float b0 = s_bias[colL], b1v = s_bias[colL + 1];
                    *reinterpret_cast<float2*>(out + ((size_t)r << 10) + col) =
                        make_float2(c[half * 2 + 0] + b0, c[half * 2 + 1] + b1v);
                }
            }
        }
    }
}

// ---------------------------------------------------------------------------
extern "C" void kernel_launch(void* const* d_in, const int* in_sizes, int n_in,
                              void* d_out, int out_size)
{
    const float* nf  = (const float*)d_in[0];
    const int*   src = (const int*)d_in[1];   // JAX int64 downcasts to int32 (x64 off)
    const int*   dst = (const int*)d_in[2];
    const float* W1  = (const float*)d_in[3];
    const float* b1  = (const float*)d_in[4];
    const float* W2  = (const float*)d_in[5];
    const float* b2  = (const float*)d_in[6];
    float*       out = (float*)d_out;

    cudaFuncSetAttribute(gemm_kernel<0>,
                         cudaFuncAttributeMaxDynamicSharedMemorySize, SMEM_BYTES);
    cudaFuncSetAttribute(gemm_kernel<1>,
                         cudaFuncAttributeMaxDynamicSharedMemorySize, SMEM_BYTES);

    // 1) convert node features to fp16
    {
        int n4 = (NNODES * DNODE) / 4;
        conv_nf_kernel<<<(n4 + 255) / 256, 256>>>((const float4*)nf, n4);
    }
    // 2) transpose weights to fp16 [N][K]
    {
        size_t t1 = (size_t)(2 * DNODE) * DHID;
        transpose_W1<<<(unsigned)((t1 + 255) / 256), 256>>>(W1);
        size_t t2 = (size_t)DHID * DHID;
        transpose_W2<<<(unsigned)((t2 + 255) / 256), 256>>>(W2);
    }
    // 3) node GEMM: P = nf @ [W1_top | W1_bot]   (M=50048, N=2048, K=1024)
    {
        dim3 grid(2 * DNODE / 128, NPAD / 128);   // (16, 391)
        gemm_kernel<0><<<grid, 256, SMEM_BYTES>>>(nullptr, nullptr);
    }
    // 4) combine: H = relu(U[src] + V[dst] + b1) -> fp16 g_H
    {
        combine_kernel<<<NEDGES, 256>>>(src, dst, b1);
    }
    // 5) stage 2: out = H @ W2 + b2   (M=65536, N=1024, K=1024)
    {
        dim3 grid(DHID / 128, NEDGES / 128);      // (8, 512)
        gemm_kernel<1><<<grid, 256, SMEM_BYTES>>>(b2, out);
    }
}

// round 16
// speedup vs baseline: 2.8077x; 1.0185x over previous
#include <cuda_runtime.h>
#include <cuda_fp16.h>
#include <cstdint>

#define NEDGES 65536
#define NNODES 50000
#define NPAD   50048          // 391 * 128
#define DNODE  1024
#define DHID   1024

// ---------------------------------------------------------------------------
// Device scratch (static). Referenced ONLY from device code — passing a
// __device__ array as a kernel argument from host passes the host shadow
// address (GB300/ATS silently writes host memory!).
// ---------------------------------------------------------------------------
__device__ __half g_nf[(size_t)NNODES * DNODE];                 // fp16
__device__ __half g_W1T[(size_t)(2 * DNODE) * DHID];            // [N'=2048][K=1024]
__device__ __half g_W2T[(size_t)DHID * DHID];                   // [N=1024][K=1024]
__device__ __half g_P[(size_t)NPAD * (2 * DNODE)];              // U|V  fp16 [NPAD][2048]
__device__ __half g_H[(size_t)NEDGES * DHID];                   // fp16

__device__ __forceinline__ uint32_t smem_u32(const void* p) {
    uint32_t a;
    asm("{ .reg .u64 t; cvta.to.shared.u64 t, %1; cvt.u32.u64 %0, t; }" : "=r"(a) : "l"(p));
    return a;
}
__device__ __forceinline__ void cp16(uint32_t saddr, const void* g) {
    asm volatile("cp.async.cg.shared.global [%0], [%1], 16;" :: "r"(saddr), "l"(g));
}
__device__ __forceinline__ void cp_commit() {
    asm volatile("cp.async.commit_group;");
}
template<int N>
__device__ __forceinline__ void cp_wait() {
    asm volatile("cp.async.wait_group %0;" :: "n"(N));
}
__device__ __forceinline__ void ldsm4(uint32_t* r, uint32_t addr) {
    asm volatile("ldmatrix.sync.aligned.m8n8.x4.shared.b16 {%0,%1,%2,%3}, [%4];"
                 : "=r"(r[0]), "=r"(r[1]), "=r"(r[2]), "=r"(r[3]) : "r"(addr));
}
__device__ __forceinline__ void mma16816(float* c, const uint32_t* a,
                                         uint32_t b0, uint32_t b1) {
    asm volatile(
        "mma.sync.aligned.m16n8k16.row.col.f32.f16.f16.f32 "
        "{%0,%1,%2,%3}, {%4,%5,%6,%7}, {%8,%9}, {%0,%1,%2,%3};"
        : "+f"(c[0]), "+f"(c[1]), "+f"(c[2]), "+f"(c[3])
        : "r"(a[0]), "r"(a[1]), "r"(a[2]), "r"(a[3]), "r"(b0), "r"(b1));
}

// ---------------------------------------------------------------------------
// Pre-pass kernels (globals written device-side)
// ---------------------------------------------------------------------------
__global__ void conv_nf_kernel(const float4* __restrict__ in, int n4)
{
    int id = blockIdx.x * blockDim.x + threadIdx.x;
    if (id >= n4) return;
    float4 v = in[id];
    __half2 p0 = __floats2half2_rn(v.x, v.y);
    __half2 p1 = __floats2half2_rn(v.z, v.w);
    *reinterpret_cast<uint2*>(g_nf + 4 * (size_t)id) =
        make_uint2(*reinterpret_cast<uint32_t*>(&p0), *reinterpret_cast<uint32_t*>(&p1));
}

// W1 [2048,1024] -> B' [n'=2048][k=1024] fp16:
//   n'<1024:  B'[n',k] = W1[k,      n']        (U = nf @ W1_top)
//   n'>=1024: B'[n',k] = W1[k+1024, n'-1024]   (V = nf @ W1_bot)
__global__ void transpose_W1(const float* __restrict__ W1)
{
    size_t id = (size_t)blockIdx.x * blockDim.x + threadIdx.x;
    if (id >= (size_t)(2 * DNODE) * DHID) return;
    int n = (int)(id >> 10);          // 0..2047
    int k = (int)(id & 1023);
    int srow = (n < DHID) ? k : (k + DNODE);
    int scol = n & (DHID - 1);
    g_W1T[id] = __float2half_rn(W1[(size_t)srow * DHID + scol]);
}

// W2 [1024,1024] -> W2T [N][K] fp16
__global__ void transpose_W2(const float* __restrict__ W2)
{
    size_t id = (size_t)blockIdx.x * blockDim.x + threadIdx.x;
    if (id >= (size_t)DHID * DHID) return;
    int k = (int)(id & 1023);
    int n = (int)(id >> 10);
    g_W2T[id] = __float2half_rn(W2[(size_t)k * DHID + n]);
}

// Combine: H[e,:] = relu(U[src[e],:] + V[dst[e],:] + b1) -> fp16 g_H.
// One block per edge, 256 threads x 4 elements (fp16 U/V).
__global__ __launch_bounds__(256)
void combine_kernel(const int* __restrict__ src, const int* __restrict__ dst,
                    const float* __restrict__ b1)
{
    const int e = blockIdx.x;
    const int t = threadIdx.x;
    const int s = src[e], d = dst[e];
    const uint2 uu = *reinterpret_cast<const uint2*>(g_P + (size_t)s * 2048 + t * 4);
    const uint2 vv = *reinterpret_cast<const uint2*>(g_P + (size_t)d * 2048 + 1024 + t * 4);
    const float4 bb = reinterpret_cast<const float4*>(b1)[t];
    float2 u0 = __half22float2(*reinterpret_cast<const __half2*>(&uu.x));
    float2 u1 = __half22float2(*reinterpret_cast<const __half2*>(&uu.y));
    float2 v0 = __half22float2(*reinterpret_cast<const __half2*>(&vv.x));
    float2 v1 = __half22float2(*reinterpret_cast<const __half2*>(&vv.y));
    float w0 = u0.x + v0.x + bb.x, w1 = u0.y + v0.y + bb.y;
    float w2 = u1.x + v1.x + bb.z, w3 = u1.y + v1.y + bb.w;
    w0 = w0 > 0.0f ? w0 : 0.0f;  w1 = w1 > 0.0f ? w1 : 0.0f;
    w2 = w2 > 0.0f ? w2 : 0.0f;  w3 = w3 > 0.0f ? w3 : 0.0f;
    __half2 p0 = __floats2half2_rn(w0, w1);
    __half2 p1 = __floats2half2_rn(w2, w3);
    *reinterpret_cast<uint2*>(g_H + ((size_t)e << 10) + t * 4) =
        make_uint2(*reinterpret_cast<uint32_t*>(&p0), *reinterpret_cast<uint32_t*>(&p1));
}

// ---------------------------------------------------------------------------
// Pure fp16 raw-MMA GEMM: D = A * B, fp32 accumulate.
//   BM=128, BN=128, BK=32; 8 warps (4m x 2n), warp tile 32x64.
//   ALL 12 fragment loads (both k16 steps) issued back-to-back before the
//   32 MMAs — LDSM latency covered by LDSM pipelining, not exposed per step.
//   cp.async double-buffered (A | B), one barrier per k-tile, 2 CTAs/SM.
//   MODE 0 (node): A = g_nf rows (clamped), out = g_P fp16 (stride 2048).
//   MODE 1 (stage2): A = g_H rows, out = param fp32 (stride 1024) + bias.
// ---------------------------------------------------------------------------
static constexpr int RSB  = 80;                 // smem row stride bytes (40 fp16)
static constexpr int MBUF = 128 * RSB;          // 10240 B: one matrix buffer
static constexpr int SBUF = 2 * MBUF;           // 20480 B: A|B
static constexpr int HDR  = 1024;               // s_bias
static constexpr int SMEM_BYTES = HDR + 2 * SBUF;   // 41984

template<int MODE>
__global__ __launch_bounds__(256, 2)
void gemm_kernel(const float* __restrict__ bias, float* __restrict__ out)
{
    extern __shared__ char smem[];
    float* s_bias = (float*)smem;
    char*  tiles  = smem + HDR;
    const uint32_t tiles_u32 = smem_u32(tiles);

    const int tid  = threadIdx.x;
    const int lane = tid & 31;
    const int wid  = tid >> 5;
    const int wm   = wid & 3;      // 4 warps along M (32 rows each)
    const int wn   = wid >> 2;     // 2 warps along N (64 cols each)
    const int m0 = blockIdx.y * 128;
    const int n0 = blockIdx.x * 128;

    if (MODE == 1 && tid < 128) s_bias[tid] = bias[n0 + tid];
    __syncthreads();

    const __half* A = (MODE == 0) ? g_nf : g_H;
    const __half* B = (MODE == 0) ? g_W1T : g_W2T;

    constexpr int NT = 32;   // K = 1024, BK = 32

    float acc[2][8][4];
    #pragma unroll
    for (int i = 0; i < 2; ++i)
        #pragma unroll
        for (int j = 0; j < 8; ++j)
            #pragma unroll
            for (int q = 0; q < 4; ++q) acc[i][j][q] = 0.0f;

    const int lrow = lane & 15;
    const int lkb  = (lane >> 4) * 16;
    const uint32_t aBase = tiles_u32 + (wm * 32 + lrow) * RSB + lkb;
    const uint32_t bBase = tiles_u32 + MBUF + (wn * 64 + lrow) * RSB + lkb;

    // A row index for loads (clamped for the padded node tail)
    const int arow_l = tid >> 1;
    int arow_g = m0 + arow_l;
    if (MODE == 0 && arow_g >= NNODES) arow_g = 0;   // padding rows: load row 0

    auto issue_tile = [&](int kt, int s) {
        const int kglob = kt * 32;
        const int half = (tid & 1) * 16;
        const uint32_t base = tiles_u32 + s * SBUF + arow_l * RSB + half * 2;
        const size_t gA = ((size_t)arow_g << 10) + kglob + half;
        const size_t gB = (size_t)(n0 + arow_l) * 1024 + kglob + half;
        #pragma unroll
        for (int ch = 0; ch < 2; ++ch) {
            cp16(base + 0 * MBUF + ch * 16, A + gA + ch * 8);
            cp16(base + 1 * MBUF + ch * 16, B + gB + ch * 8);
        }
    };

    auto compute = [&](int s) {
        const uint32_t aB = aBase + s * SBUF;
        const uint32_t bB = bBase + s * SBUF;
        uint32_t ah[2][2][4], b[2][4][4];   // [kk][...]
        // ---- all 12 LDSMs back-to-back: latency mutually covered ----
        #pragma unroll
        for (int kk = 0; kk < 2; ++kk) {
            const uint32_t cb = kk * 32;
            ldsm4(ah[kk][0], aB + cb);
            ldsm4(ah[kk][1], aB + 16 * RSB + cb);
            #pragma unroll
            for (int j = 0; j < 4; ++j)
                ldsm4(b[kk][j], bB + j * 16 * RSB + cb);
        }
        // ---- then all 32 MMAs ----
        #pragma unroll
        for (int kk = 0; kk < 2; ++kk)
            #pragma unroll
            for (int mi = 0; mi < 2; ++mi)
                #pragma unroll
                for (int j = 0; j < 4; ++j)
                    #pragma unroll
                    for (int s2 = 0; s2 < 2; ++s2)
                        mma16816(acc[mi][j * 2 + s2], ah[kk][mi],
                                 b[kk][j][s2], b[kk][j][s2 + 2]);
    };

    issue_tile(0, 0);
    cp_commit();
    for (int kt = 0; kt < NT; ++kt) {
        cp_wait<0>();
        __syncthreads();
        if (kt + 1 < NT) {
            issue_tile(kt + 1, (kt + 1) & 1);
            cp_commit();
        }
        compute(kt & 1);
    }

    // ---- direct register epilogue ----
    const int grp = lane >> 2, tg = lane & 3;
    #pragma unroll
    for (int mi = 0; mi < 2; ++mi) {
        const int rbase = m0 + wm * 32 + mi * 16 + grp;
        #pragma unroll
        for (int n8 = 0; n8 < 8; ++n8) {
            const float* c = acc[mi][n8];
            const int colL = wn * 64 + n8 * 8 + tg * 2;
            const int col  = n0 + colL;
            #pragma unroll
            for (int half = 0; half < 2; ++half) {
                const int r = rbase + half * 8;
                if (MODE == 0) {
                    // P fp16, row stride 2048 (skip padded rows)
                    if (r < NNODES) {
                        __half2 p = __floats2half2_rn(c[half * 2 + 0], c[half * 2 + 1]);
                        *reinterpret_cast<uint32_t*>(g_P + (size_t)r * 2048 + col) =
                            *reinterpret_cast<uint32_t*>(&p);
                    }
                } else {
                    const float b0 = s_bias[colL], b1v = s_bias[colL + 1];
                    *reinterpret_cast<float2*>(out + ((size_t)r << 10) + col) =
                        make_float2(c[half * 2 + 0] + b0, c[half * 2 + 1] + b1v);
                }
            }
        }
    }
}

// ---------------------------------------------------------------------------
extern "C" void kernel_launch(void* const* d_in, const int* in_sizes, int n_in,
                              void* d_out, int out_size)
{
    const float* nf  = (const float*)d_in[0];
    const int*   src = (const int*)d_in[1];   // JAX int64 downcasts to int32 (x64 off)
    const int*   dst = (const int*)d_in[2];
    const float* W1  = (const float*)d_in[3];
    const float* b1  = (const float*)d_in[4];
    const float* W2  = (const float*)d_in[5];
    const float* b2  = (const float*)d_in[6];
    float*       out = (float*)d_out;

    cudaFuncSetAttribute(gemm_kernel<0>,
                         cudaFuncAttributeMaxDynamicSharedMemorySize, SMEM_BYTES);
    cudaFuncSetAttribute(gemm_kernel<1>,
                         cudaFuncAttributeMaxDynamicSharedMemorySize, SMEM_BYTES);

    // 1) convert node features to fp16
    {
        int n4 = (NNODES * DNODE) / 4;
        conv_nf_kernel<<<(n4 + 255) / 256, 256>>>((const float4*)nf, n4);
    }
    // 2) transpose weights to fp16 [N][K]
    {
        size_t t1 = (size_t)(2 * DNODE) * DHID;
        transpose_W1<<<(unsigned)((t1 + 255) / 256), 256>>>(W1);
        size_t t2 = (size_t)DHID * DHID;
        transpose_W2<<<(unsigned)((t2 + 255) / 256), 256>>>(W2);
    }
    // 3) node GEMM: P = nf @ [W1_top | W1_bot]   (M=50048, N=2048, K=1024)
    {
        dim3 grid(2 * DNODE / 128, NPAD / 128);   // (16, 391)
        gemm_kernel<0><<<grid, 256, SMEM_BYTES>>>(nullptr, nullptr);
    }
    // 4) combine: H = relu(U[src] + V[dst] + b1) -> fp16 g_H
    {
        combine_kernel<<<NEDGES, 256>>>(src, dst, b1);
    }
    // 5) stage 2: out = H @ W2 + b2   (M=65536, N=1024, K=1024)
    {
        dim3 grid(DHID / 128, NEDGES / 128);      // (8, 512)
        gemm_kernel<1><<<grid, 256, SMEM_BYTES>>>(b2, out);
    }
}